// round 2
// baseline (speedup 1.0000x reference)
#include <cuda_runtime.h>
#include <cuda_bf16.h>
#include <mma.h>
#include <math.h>

using namespace nvcuda;

// Problem constants (shapes fixed by the dataset)
#define BATCH   512
#define HID     1024
#define GATES   4096          // 4*HID
#define KDIM    1024          // = HID (recurrent GEMM K)

// GEMM tiling
#define BM      128           // batch rows per CTA
#define NH      32            // hidden units per CTA -> effective N = 4*NH = 128
#define BK      32            // K chunk
#define APAD    40            // smem row stride (elements) for bf16 tiles
#define BUFLD   132           // smem row stride for fp32 gate buffer
#define SMEM_BYTES (BM * BUFLD * 4)   // 67584: gate buffer (tiles fit underneath it)

// ---------------- scratch (static device allocations) ----------------
__device__ float          g_h   [BATCH * HID];
__device__ float          g_c   [BATCH * HID];
__device__ __nv_bfloat16  g_hhi [BATCH * HID];
__device__ __nv_bfloat16  g_hlo [BATCH * HID];
__device__ __nv_bfloat16  g_Whi [GATES * KDIM];
__device__ __nv_bfloat16  g_Wlo [GATES * KDIM];
__device__ float          g_pred[BATCH];

// ---------------- prep: split W_hh into bf16 hi/lo ----------------
__global__ void prep_split_kernel(const float* __restrict__ W) {
    int n = GATES * KDIM;
    for (int i = blockIdx.x * blockDim.x + threadIdx.x; i < n; i += gridDim.x * blockDim.x) {
        float w = W[i];
        __nv_bfloat16 hi = __float2bfloat16(w);
        g_Whi[i] = hi;
        g_Wlo[i] = __float2bfloat16(w - __bfloat162float(hi));
    }
}

// ---------------- init: zero h, c, h splits ----------------
__global__ void init_zero_kernel() {
    int n = BATCH * HID;
    __nv_bfloat16 z = __float2bfloat16(0.0f);
    for (int i = blockIdx.x * blockDim.x + threadIdx.x; i < n; i += gridDim.x * blockDim.x) {
        g_h[i] = 0.0f;
        g_c[i] = 0.0f;
        g_hhi[i] = z;
        g_hlo[i] = z;
    }
}

__device__ __forceinline__ float sigf(float x) { return 1.0f / (1.0f + expf(-x)); }

// ---------------- one LSTM step: gates GEMM (split-bf16 WMMA) + cell update ----------------
// grid: (BATCH/BM, HID/NH) = (4, 32), block: 256 threads (8 warps)
__global__ void __launch_bounds__(256, 1)
lstm_step_kernel(const float* __restrict__ x, int xstride,
                 const float* __restrict__ W_ih,
                 const float* __restrict__ b_ih,
                 const float* __restrict__ b_hh) {
    extern __shared__ __align__(128) char smem_raw[];
    __nv_bfloat16* Ahi = (__nv_bfloat16*)smem_raw;            // [BM][APAD]
    __nv_bfloat16* Alo = Ahi + BM * APAD;
    __nv_bfloat16* Bhi = Alo + BM * APAD;                      // 128 gathered W rows
    __nv_bfloat16* Blo = Bhi + BM * APAD;
    float* gbuf = (float*)smem_raw;                            // [BM][BUFLD], reused after GEMM

    const int tid = threadIdx.x;
    const int wid = tid >> 5;
    const int m0  = blockIdx.x * BM;       // batch row base
    const int j0  = blockIdx.y * NH;       // hidden col base

    const int warpRow = wid >> 1;          // 0..3 -> 32-row slab
    const int warpCol = wid & 1;           // 0..1 -> 64-col slab

    wmma::fragment<wmma::accumulator, 16, 16, 16, float> acc[2][4];
#pragma unroll
    for (int i = 0; i < 2; ++i)
#pragma unroll
        for (int j = 0; j < 4; ++j)
            wmma::fill_fragment(acc[i][j], 0.0f);

    for (int k0 = 0; k0 < KDIM; k0 += BK) {
        // ---- load tiles: A (h hi/lo) rows m0..m0+127, B (W hi/lo) gathered rows ----
        // each matrix = 128 rows x 32 bf16 = 1024 uint2; 256 threads -> 4 uint2 each
#pragma unroll
        for (int it = 0; it < 4; ++it) {
            int li = tid + it * 256;            // 0..1023
            int r  = li >> 3;                   // 0..127
            int c  = (li & 7) * 4;              // bf16 col offset 0..28

            size_t aoff = (size_t)(m0 + r) * KDIM + k0 + c;
            *(uint2*)(Ahi + r * APAD + c) = *(const uint2*)(g_hhi + aoff);
            *(uint2*)(Alo + r * APAD + c) = *(const uint2*)(g_hlo + aoff);

            int seg = r >> 5;                   // gate segment 0..3
            int wrow = seg * HID + j0 + (r & 31);
            size_t boff = (size_t)wrow * KDIM + k0 + c;
            *(uint2*)(Bhi + r * APAD + c) = *(const uint2*)(g_Whi + boff);
            *(uint2*)(Blo + r * APAD + c) = *(const uint2*)(g_Wlo + boff);
        }
        __syncthreads();

#pragma unroll
        for (int kk = 0; kk < BK; kk += 16) {
            wmma::fragment<wmma::matrix_a, 16, 16, 16, __nv_bfloat16, wmma::row_major> ahi[2], alo[2];
#pragma unroll
            for (int i = 0; i < 2; ++i) {
                const __nv_bfloat16* ap = Ahi + (warpRow * 32 + i * 16) * APAD + kk;
                wmma::load_matrix_sync(ahi[i], ap, APAD);
                const __nv_bfloat16* ap2 = Alo + (warpRow * 32 + i * 16) * APAD + kk;
                wmma::load_matrix_sync(alo[i], ap2, APAD);
            }
#pragma unroll
            for (int j = 0; j < 4; ++j) {
                wmma::fragment<wmma::matrix_b, 16, 16, 16, __nv_bfloat16, wmma::col_major> bhi, blo;
                const __nv_bfloat16* bp = Bhi + (warpCol * 64 + j * 16) * APAD + kk;
                wmma::load_matrix_sync(bhi, bp, APAD);
                const __nv_bfloat16* bp2 = Blo + (warpCol * 64 + j * 16) * APAD + kk;
                wmma::load_matrix_sync(blo, bp2, APAD);
#pragma unroll
                for (int i = 0; i < 2; ++i) {
                    wmma::mma_sync(acc[i][j], ahi[i], bhi, acc[i][j]);
                    wmma::mma_sync(acc[i][j], ahi[i], blo, acc[i][j]);
                    wmma::mma_sync(acc[i][j], alo[i], bhi, acc[i][j]);
                }
            }
        }
        __syncthreads();
    }

    // ---- dump accumulators to smem gate buffer ----
#pragma unroll
    for (int i = 0; i < 2; ++i)
#pragma unroll
        for (int j = 0; j < 4; ++j)
            wmma::store_matrix_sync(gbuf + (warpRow * 32 + i * 16) * BUFLD + warpCol * 64 + j * 16,
                                    acc[i][j], BUFLD, wmma::mem_row_major);
    __syncthreads();

    // ---- cell update: 128 batch x 32 hidden units per CTA ----
#pragma unroll
    for (int it = 0; it < 16; ++it) {
        int li = tid + it * 256;               // 0..4095
        int b  = li >> 5;                      // local batch 0..127
        int jj = li & 31;                      // local hidden 0..31
        int gb = m0 + b;
        int j  = j0 + jj;

        float xv = x[(size_t)gb * xstride];

        float gi = gbuf[b * BUFLD +      jj] + xv * W_ih[         j] + b_ih[         j] + b_hh[         j];
        float gf = gbuf[b * BUFLD + 32 + jj] + xv * W_ih[  HID + j] + b_ih[  HID + j] + b_hh[  HID + j];
        float gg = gbuf[b * BUFLD + 64 + jj] + xv * W_ih[2*HID + j] + b_ih[2*HID + j] + b_hh[2*HID + j];
        float go = gbuf[b * BUFLD + 96 + jj] + xv * W_ih[3*HID + j] + b_ih[3*HID + j] + b_hh[3*HID + j];

        size_t idx = (size_t)gb * HID + j;
        float c_old = g_c[idx];
        float c_new = sigf(gf) * c_old + sigf(gi) * tanhf(gg);
        float h_new = sigf(go) * tanhf(c_new);

        g_c[idx] = c_new;
        g_h[idx] = h_new;
        __nv_bfloat16 hi = __float2bfloat16(h_new);
        g_hhi[idx] = hi;
        g_hlo[idx] = __float2bfloat16(h_new - __bfloat162float(hi));
    }
}

// ---------------- readout: pred[b] = h[b,:] . W_out + b_out ----------------
// grid: 64 CTAs x 256 threads = 512 warps, one warp per batch row
__global__ void pred_kernel(const float* __restrict__ W_out,
                            const float* __restrict__ b_out,
                            float* __restrict__ out, int s, int steps) {
    int warp = (blockIdx.x * blockDim.x + threadIdx.x) >> 5;
    int lane = threadIdx.x & 31;
    if (warp >= BATCH) return;
    const float* hr = g_h + (size_t)warp * HID;
    float sum = 0.0f;
#pragma unroll 8
    for (int k = lane; k < HID; k += 32) sum += hr[k] * W_out[k];
#pragma unroll
    for (int off = 16; off > 0; off >>= 1) sum += __shfl_down_sync(0xFFFFFFFFu, sum, off);
    if (lane == 0) {
        float p = sum + b_out[0];
        g_pred[warp] = p;
        out[(size_t)warp * steps + s] = p;
    }
}

// ---------------- launch ----------------
extern "C" void kernel_launch(void* const* d_in, const int* in_sizes, int n_in,
                              void* d_out, int out_size) {
    const float* data  = (const float*)d_in[0];  // [B, T, 1]
    const float* W_ih  = (const float*)d_in[1];  // [4H, 1]
    const float* W_hh  = (const float*)d_in[2];  // [4H, H]
    const float* b_ih  = (const float*)d_in[3];  // [4H]
    const float* b_hh  = (const float*)d_in[4];  // [4H]
    const float* W_out = (const float*)d_in[5];  // [1, H]
    const float* b_out = (const float*)d_in[6];  // [1]
    float* out = (float*)d_out;                  // [B, STEPS, 1]

    int T     = in_sizes[0] / BATCH;   // 64
    int steps = out_size / BATCH;      // 96

    cudaFuncSetAttribute(lstm_step_kernel,
                         cudaFuncAttributeMaxDynamicSharedMemorySize, SMEM_BYTES);

    float* pred_ptr = nullptr;
    cudaGetSymbolAddress((void**)&pred_ptr, g_pred);

    prep_split_kernel<<<4096, 512>>>(W_hh);
    init_zero_kernel<<<1024, 512>>>();

    dim3 grid(BATCH / BM, HID / NH);   // (4, 32)

    // Phase 1: warmup over the input sequence (x_t = data[:, t, 0], stride T)
    for (int t = 0; t < T; ++t)
        lstm_step_kernel<<<grid, 256, SMEM_BYTES>>>(data + t, T, W_ih, b_ih, b_hh);

    // prediction at step 0 (also becomes next input)
    pred_kernel<<<64, 256>>>(W_out, b_out, out, 0, steps);

    // Phase 2: autoregressive decode
    for (int s = 1; s < steps; ++s) {
        lstm_step_kernel<<<grid, 256, SMEM_BYTES>>>(pred_ptr, 1, W_ih, b_ih, b_hh);
        pred_kernel<<<64, 256>>>(W_out, b_out, out, s, steps);
    }
}

// round 6
// speedup vs baseline: 1.7232x; 1.7232x over previous
#include <cuda_runtime.h>
#include <cuda_bf16.h>
#include <cstdint>
#include <math.h>

#define BATCH 512
#define HID   1024
#define GATES 4096
#define TILEM 128          // batch rows per CTA
#define NH    32           // hidden units per CTA (-> 128 gate cols)
#define KC    64           // K chunk (bf16 elems), 128B rows
#define NCHUNK (HID / KC)  // 16
#define NSTAGE 3

// ---- shared memory layout (bytes) ----
#define SO_X      0         // 128 f32
#define SO_WIH    512       // 128 f32
#define SO_BSUM   1024      // 128 f32
#define SO_WOUT   1536      // 32 f32
#define SO_STAGE  2048
#define STAGE_BYTES 65536   // 4 matrices x 128 x 64 bf16 (16KB each)
#define TO_AHI    0
#define TO_ALO    16384
#define TO_BHI    32768
#define TO_BLO    49152
#define SMEM_TOTAL (SO_STAGE + NSTAGE * STAGE_BYTES)   // 198656
#define GBUF_LD   132       // f32 stride of gate buffer (reuses stage mem)

// ---------------- device scratch ----------------
__device__ __align__(128) float          g_c   [BATCH * HID];
__device__ __align__(128) __nv_bfloat16  g_hhi [BATCH * HID];
__device__ __align__(128) __nv_bfloat16  g_hlo [BATCH * HID];
__device__ __align__(128) __nv_bfloat16  g_Whi [GATES * HID];
__device__ __align__(128) __nv_bfloat16  g_Wlo [GATES * HID];
__device__ __align__(128) float          g_parts[32 * BATCH];

// ---------------- helpers ----------------
__device__ __forceinline__ uint32_t smem_u32(const void* p) {
    uint32_t a;
    asm("{ .reg .u64 t; cvta.to.shared.u64 t, %1; cvt.u32.u64 %0, t; }" : "=r"(a) : "l"(p));
    return a;
}
__device__ __forceinline__ void cp16(uint32_t dst, const void* src) {
    asm volatile("cp.async.cg.shared.global [%0], [%1], 16;"
                 :: "r"(dst), "l"(__cvta_generic_to_global(src)));
}
__device__ __forceinline__ uint32_t swz(uint32_t off) { return off ^ ((off >> 3) & 0x70); }

__device__ __forceinline__ void ldsm4(uint32_t* r, uint32_t a) {
    asm volatile("ldmatrix.sync.aligned.m8n8.x4.shared.b16 {%0,%1,%2,%3}, [%4];"
                 : "=r"(r[0]), "=r"(r[1]), "=r"(r[2]), "=r"(r[3]) : "r"(a));
}
__device__ __forceinline__ void hmma(float* c, const uint32_t* a, const uint32_t* b) {
    asm volatile("mma.sync.aligned.m16n8k16.row.col.f32.bf16.bf16.f32 "
                 "{%0,%1,%2,%3}, {%4,%5,%6,%7}, {%8,%9}, {%0,%1,%2,%3};"
                 : "+f"(c[0]), "+f"(c[1]), "+f"(c[2]), "+f"(c[3])
                 : "r"(a[0]), "r"(a[1]), "r"(a[2]), "r"(a[3]), "r"(b[0]), "r"(b[1]));
}
__device__ __forceinline__ float sigf(float x) { return 1.0f / (1.0f + expf(-x)); }

// ---------------- prep / init ----------------
__global__ void prep_split_kernel(const float* __restrict__ W) {
    int n = GATES * HID;
    for (int i = blockIdx.x * blockDim.x + threadIdx.x; i < n; i += gridDim.x * blockDim.x) {
        float w = W[i];
        __nv_bfloat16 hi = __float2bfloat16(w);
        g_Whi[i] = hi;
        g_Wlo[i] = __float2bfloat16(w - __bfloat162float(hi));
    }
}
__global__ void init_zero_kernel() {
    int n = BATCH * HID;
    __nv_bfloat16 z = __float2bfloat16(0.0f);
    for (int i = blockIdx.x * blockDim.x + threadIdx.x; i < n; i += gridDim.x * blockDim.x) {
        g_c[i] = 0.0f; g_hhi[i] = z; g_hlo[i] = z;
    }
}

// ---------------- one LSTM step (mma.sync pipeline) ----------------
// grid (4, 32), block 256.
__global__ void __launch_bounds__(256, 1)
lstm_step(int mode, const float* __restrict__ x, int xstride, int sprev, int steps,
          const float* __restrict__ W_ih, const float* __restrict__ b_ih,
          const float* __restrict__ b_hh, const float* __restrict__ W_out,
          const float* __restrict__ b_out, float* __restrict__ out)
{
    extern __shared__ __align__(1024) char sm[];
    const uint32_t sb = smem_u32(sm);
    const int tid  = threadIdx.x;
    const int wid  = tid >> 5;
    const int lane = tid & 31;
    const int m0 = blockIdx.x * TILEM;
    const int j0 = blockIdx.y * NH;
    const int wM = wid & 1;        // 0..1 -> 64-row slab
    const int wN = wid >> 1;       // 0..3 -> 32-col slab

    float* s_x    = (float*)(sm + SO_X);
    float* s_wih  = (float*)(sm + SO_WIH);
    float* s_bsum = (float*)(sm + SO_BSUM);
    float* s_wout = (float*)(sm + SO_WOUT);
    float* gbuf   = (float*)(sm + SO_STAGE);   // reused after mainloop

    // ---- prologue: x / wih / biases / wout into SMEM ----
    if (tid < 128) {
        int r = tid;
        float xv;
        if (mode == 0) {
            xv = x[(size_t)(m0 + r) * xstride];
        } else {
            float acc = 0.0f;
#pragma unroll 8
            for (int p = 0; p < 32; ++p) acc += g_parts[p * BATCH + m0 + r];
            xv = acc + b_out[0];
            if (blockIdx.y == 0) out[(size_t)(m0 + r) * steps + sprev] = xv;
        }
        s_x[r] = xv;
        int g = tid >> 5, jj = tid & 31;
        int j = g * HID + j0 + jj;
        s_wih[tid]  = W_ih[j];
        s_bsum[tid] = b_ih[j] + b_hh[j];
    } else if (tid < 160) {
        s_wout[tid - 128] = W_out[j0 + tid - 128];
    }

    // per-thread ldmatrix UNSWIZZLED base offsets (swizzle applied per-access)
    const uint32_t aU = (uint32_t)((wM * 64 + (lane & 15)) * 128 + ((lane >> 4) * 8) * 2);
    const uint32_t bU = (uint32_t)((wN * 32 + (lane & 7) + ((lane >> 4) << 3)) * 128
                                   + (((lane >> 3) & 1) * 8) * 2);

    float acc[4][4][4];
#pragma unroll
    for (int mt = 0; mt < 4; ++mt)
#pragma unroll
        for (int nt = 0; nt < 4; ++nt)
#pragma unroll
            for (int e = 0; e < 4; ++e) acc[mt][nt][e] = 0.0f;

    // ---- chunk loader ----
    auto load_chunk = [&](int chunk, uint32_t stg) {
        const int k0 = chunk * KC;
#pragma unroll
        for (int it = 0; it < 4; ++it) {
            int li = it * 256 + tid;
            int r = li >> 3, c16 = li & 7;
            uint32_t soff = swz((uint32_t)(r * 128 + c16 * 16));
            size_t aoff = (size_t)(m0 + r) * HID + k0 + c16 * 8;
            cp16(stg + TO_AHI + soff, g_hhi + aoff);
            cp16(stg + TO_ALO + soff, g_hlo + aoff);
            size_t boff = (size_t)((r >> 5) * HID + j0 + (r & 31)) * HID + k0 + c16 * 8;
            cp16(stg + TO_BHI + soff, g_Whi + boff);
            cp16(stg + TO_BLO + soff, g_Wlo + boff);
        }
    };
    // ---- chunk compute ----
    auto compute_chunk = [&](uint32_t stg) {
#pragma unroll
        for (int k16 = 0; k16 < 4; ++k16) {
            const uint32_t ko = (uint32_t)k16 * 32;   // 16 bf16 = 32 bytes along K
            uint32_t aHi[4][4], aLo[4][4];
#pragma unroll
            for (int mt = 0; mt < 4; ++mt) {
                uint32_t so = swz(aU + (uint32_t)mt * 2048 + ko);
                ldsm4(aHi[mt], stg + TO_AHI + so);
                ldsm4(aLo[mt], stg + TO_ALO + so);
            }
            uint32_t bH[4][2], bL[4][2];
#pragma unroll
            for (int half = 0; half < 2; ++half) {
                uint32_t so = swz(bU + (uint32_t)half * 2048 + ko);
                uint32_t t[4];
                ldsm4(t, stg + TO_BHI + so);        // non-trans: B stored [N][K], K contiguous
                bH[half*2][0] = t[0]; bH[half*2][1] = t[1];
                bH[half*2+1][0] = t[2]; bH[half*2+1][1] = t[3];
                ldsm4(t, stg + TO_BLO + so);
                bL[half*2][0] = t[0]; bL[half*2][1] = t[1];
                bL[half*2+1][0] = t[2]; bL[half*2+1][1] = t[3];
            }
#pragma unroll
            for (int mt = 0; mt < 4; ++mt)
#pragma unroll
                for (int nt = 0; nt < 4; ++nt) {
                    hmma(acc[mt][nt], aHi[mt], bH[nt]);
                    hmma(acc[mt][nt], aHi[mt], bL[nt]);
                    hmma(acc[mt][nt], aLo[mt], bH[nt]);
                }
        }
    };

    const uint32_t stg0 = sb + SO_STAGE;
    // prime pipeline: chunks 0,1
    load_chunk(0, stg0);
    asm volatile("cp.async.commit_group;");
    load_chunk(1, stg0 + STAGE_BYTES);
    asm volatile("cp.async.commit_group;");

    for (int i = 0; i < NCHUNK; ++i) {
        if (i + 2 < NCHUNK) {
            load_chunk(i + 2, stg0 + ((i + 2) % 3) * STAGE_BYTES);
            asm volatile("cp.async.commit_group;");
            asm volatile("cp.async.wait_group 2;");
        } else if (i + 2 == NCHUNK) {
            asm volatile("cp.async.wait_group 1;");
        } else {
            asm volatile("cp.async.wait_group 0;");
        }
        __syncthreads();
        compute_chunk(stg0 + (i % 3) * STAGE_BYTES);
        __syncthreads();
    }

    // ---- accumulators -> gate buffer (f32) ----
#pragma unroll
    for (int mt = 0; mt < 4; ++mt)
#pragma unroll
        for (int nt = 0; nt < 4; ++nt) {
            int row = wM * 64 + mt * 16 + (lane >> 2);
            int col = wN * 32 + nt * 8 + (lane & 3) * 2;
            gbuf[row * GBUF_LD + col]           = acc[mt][nt][0];
            gbuf[row * GBUF_LD + col + 1]       = acc[mt][nt][1];
            gbuf[(row + 8) * GBUF_LD + col]     = acc[mt][nt][2];
            gbuf[(row + 8) * GBUF_LD + col + 1] = acc[mt][nt][3];
        }
    __syncthreads();

    // ---- cell update + fused readout partials ----
#pragma unroll
    for (int it = 0; it < 16; ++it) {
        int li = it * 256 + tid;
        int b  = li >> 5;          // same for all lanes of a warp
        int jj = li & 31;          // = lane

        float xv = s_x[b];
        float gi = gbuf[b * GBUF_LD +      jj] + xv * s_wih[jj]      + s_bsum[jj];
        float gf = gbuf[b * GBUF_LD + 32 + jj] + xv * s_wih[32 + jj] + s_bsum[32 + jj];
        float gg = gbuf[b * GBUF_LD + 64 + jj] + xv * s_wih[64 + jj] + s_bsum[64 + jj];
        float go = gbuf[b * GBUF_LD + 96 + jj] + xv * s_wih[96 + jj] + s_bsum[96 + jj];

        size_t idx = (size_t)(m0 + b) * HID + j0 + jj;
        float c_old = g_c[idx];
        float c_new = sigf(gf) * c_old + sigf(gi) * tanhf(gg);
        float h_new = sigf(go) * tanhf(c_new);

        g_c[idx] = c_new;
        __nv_bfloat16 hi = __float2bfloat16(h_new);
        g_hhi[idx] = hi;
        g_hlo[idx] = __float2bfloat16(h_new - __bfloat162float(hi));

        // readout partial: sum over this CTA's 32 hidden cols
        float p = h_new * s_wout[jj];
#pragma unroll
        for (int off = 16; off > 0; off >>= 1) p += __shfl_xor_sync(0xFFFFFFFFu, p, off);
        if (lane == 0) g_parts[blockIdx.y * BATCH + m0 + b] = p;
    }
}

// ---------------- final prediction (last step's readout) ----------------
__global__ void pred_final(const float* __restrict__ b_out, float* __restrict__ out, int steps) {
    int b = blockIdx.x * blockDim.x + threadIdx.x;
    if (b < BATCH) {
        float acc = 0.0f;
#pragma unroll 8
        for (int p = 0; p < 32; ++p) acc += g_parts[p * BATCH + b];
        out[(size_t)b * steps + (steps - 1)] = acc + b_out[0];
    }
}

// ---------------- launch ----------------
extern "C" void kernel_launch(void* const* d_in, const int* in_sizes, int n_in,
                              void* d_out, int out_size) {
    const float* data  = (const float*)d_in[0];  // [B, T, 1]
    const float* W_ih  = (const float*)d_in[1];  // [4H, 1]
    const float* W_hh  = (const float*)d_in[2];  // [4H, H]
    const float* b_ih  = (const float*)d_in[3];
    const float* b_hh  = (const float*)d_in[4];
    const float* W_out = (const float*)d_in[5];  // [1, H]
    const float* b_out = (const float*)d_in[6];
    float* out = (float*)d_out;                  // [B, STEPS, 1]

    int T     = in_sizes[0] / BATCH;   // 64
    int steps = out_size / BATCH;      // 96

    cudaFuncSetAttribute(lstm_step, cudaFuncAttributeMaxDynamicSharedMemorySize, SMEM_TOTAL);

    prep_split_kernel<<<2048, 512>>>(W_hh);
    init_zero_kernel<<<512, 512>>>();

    dim3 grid(BATCH / TILEM, HID / NH);   // (4, 32)

    // warmup over the input sequence
    for (int t = 0; t < T; ++t)
        lstm_step<<<grid, 256, SMEM_TOTAL>>>(0, data + t, T, 0, steps,
                                             W_ih, b_ih, b_hh, W_out, b_out, out);
    // autoregressive decode: step s consumes pred_{s-1} (parts) and writes out[:, s-1]
    for (int s = 1; s < steps; ++s)
        lstm_step<<<grid, 256, SMEM_TOTAL>>>(1, nullptr, 0, s - 1, steps,
                                             W_ih, b_ih, b_hh, W_out, b_out, out);
    // final readout out[:, steps-1]
    pred_final<<<(BATCH + 255) / 256, 256>>>(b_out, out, steps);
}

// round 7
// speedup vs baseline: 1.7870x; 1.0371x over previous
#include <cuda_runtime.h>
#include <cuda_bf16.h>
#include <cstdint>
#include <math.h>

#define BATCH 512
#define HID   1024
#define GATES 4096
#define TILEM 128          // batch rows per CTA
#define NH    32           // hidden units per CTA (-> 128 gate cols)
#define KC    64           // K chunk (bf16 elems), 128B rows
#define NCHUNK (HID / KC)  // 16
#define NSTAGE 3
#define NTHREADS 512       // 16 warps, warp tile 32x32

// ---- shared memory layout (bytes) ----
#define SO_X      0         // 128 f32
#define SO_WIH    512       // 128 f32
#define SO_BSUM   1024      // 128 f32
#define SO_WOUT   1536      // 32 f32
#define SO_STAGE  2048
#define STAGE_BYTES 65536   // 4 matrices x 128 x 64 bf16 (16KB each)
#define TO_AHI    0
#define TO_ALO    16384
#define TO_BHI    32768
#define TO_BLO    49152
#define SMEM_TOTAL (SO_STAGE + NSTAGE * STAGE_BYTES)   // 198656
#define GBUF_LD   132       // f32 stride of gate buffer (reuses stage mem)

// ---------------- device scratch ----------------
__device__ __align__(128) float          g_c   [BATCH * HID];
__device__ __align__(128) __nv_bfloat16  g_hhi [BATCH * HID];
__device__ __align__(128) __nv_bfloat16  g_hlo [BATCH * HID];
__device__ __align__(128) __nv_bfloat16  g_Whi [GATES * HID];
__device__ __align__(128) __nv_bfloat16  g_Wlo [GATES * HID];
__device__ __align__(128) float          g_parts[32 * BATCH];

// ---------------- helpers ----------------
__device__ __forceinline__ uint32_t smem_u32(const void* p) {
    uint32_t a;
    asm("{ .reg .u64 t; cvta.to.shared.u64 t, %1; cvt.u32.u64 %0, t; }" : "=r"(a) : "l"(p));
    return a;
}
__device__ __forceinline__ void cp16(uint32_t dst, const void* src) {
    asm volatile("cp.async.cg.shared.global [%0], [%1], 16;"
                 :: "r"(dst), "l"(__cvta_generic_to_global(src)));
}
__device__ __forceinline__ uint32_t swz(uint32_t off) { return off ^ ((off >> 3) & 0x70); }

__device__ __forceinline__ void ldsm4(uint32_t* r, uint32_t a) {
    asm volatile("ldmatrix.sync.aligned.m8n8.x4.shared.b16 {%0,%1,%2,%3}, [%4];"
                 : "=r"(r[0]), "=r"(r[1]), "=r"(r[2]), "=r"(r[3]) : "r"(a));
}
__device__ __forceinline__ void hmma(float* c, const uint32_t* a, const uint32_t* b) {
    asm volatile("mma.sync.aligned.m16n8k16.row.col.f32.bf16.bf16.f32 "
                 "{%0,%1,%2,%3}, {%4,%5,%6,%7}, {%8,%9}, {%0,%1,%2,%3};"
                 : "+f"(c[0]), "+f"(c[1]), "+f"(c[2]), "+f"(c[3])
                 : "r"(a[0]), "r"(a[1]), "r"(a[2]), "r"(a[3]), "r"(b[0]), "r"(b[1]));
}
__device__ __forceinline__ float sigf(float x) { return 1.0f / (1.0f + expf(-x)); }

// ---------------- prep / init ----------------
__global__ void prep_split_kernel(const float* __restrict__ W) {
    int n = GATES * HID;
    for (int i = blockIdx.x * blockDim.x + threadIdx.x; i < n; i += gridDim.x * blockDim.x) {
        float w = W[i];
        __nv_bfloat16 hi = __float2bfloat16(w);
        g_Whi[i] = hi;
        g_Wlo[i] = __float2bfloat16(w - __bfloat162float(hi));
    }
}
__global__ void init_zero_kernel() {
    int n = BATCH * HID;
    __nv_bfloat16 z = __float2bfloat16(0.0f);
    for (int i = blockIdx.x * blockDim.x + threadIdx.x; i < n; i += gridDim.x * blockDim.x) {
        g_c[i] = 0.0f; g_hhi[i] = z; g_hlo[i] = z;
    }
}

// ---------------- one LSTM step (mma.sync pipeline) ----------------
// grid (4, 32), block 512 (16 warps, warp tile 32x32).
__global__ void __launch_bounds__(NTHREADS, 1)
lstm_step(int mode, const float* __restrict__ x, int xstride, int sprev, int steps,
          const float* __restrict__ W_ih, const float* __restrict__ b_ih,
          const float* __restrict__ b_hh, const float* __restrict__ W_out,
          const float* __restrict__ b_out, float* __restrict__ out)
{
    extern __shared__ __align__(1024) char sm[];
    const uint32_t sb = smem_u32(sm);
    const int tid  = threadIdx.x;
    const int wid  = tid >> 5;
    const int lane = tid & 31;
    const int m0 = blockIdx.x * TILEM;
    const int j0 = blockIdx.y * NH;
    const int wM = wid & 3;        // 0..3 -> 32-row slab
    const int wN = wid >> 2;       // 0..3 -> 32-col slab

    float* s_x    = (float*)(sm + SO_X);
    float* s_wih  = (float*)(sm + SO_WIH);
    float* s_bsum = (float*)(sm + SO_BSUM);
    float* s_wout = (float*)(sm + SO_WOUT);
    float* gbuf   = (float*)(sm + SO_STAGE);   // reused after mainloop

    // ---- prologue: x / wih / biases / wout into SMEM ----
    if (tid < 128) {
        int r = tid;
        float xv;
        if (mode == 0) {
            xv = x[(size_t)(m0 + r) * xstride];
        } else {
            float acc = 0.0f;
#pragma unroll 8
            for (int p = 0; p < 32; ++p) acc += g_parts[p * BATCH + m0 + r];
            xv = acc + b_out[0];
            if (blockIdx.y == 0) out[(size_t)(m0 + r) * steps + sprev] = xv;
        }
        s_x[r] = xv;
        int g = tid >> 5, jj = tid & 31;
        int j = g * HID + j0 + jj;
        s_wih[tid]  = W_ih[j];
        s_bsum[tid] = b_ih[j] + b_hh[j];
    } else if (tid < 160) {
        s_wout[tid - 128] = W_out[j0 + tid - 128];
    }

    // per-thread ldmatrix UNSWIZZLED base offsets (swizzle applied per-access)
    const uint32_t aU = (uint32_t)((wM * 32 + (lane & 15)) * 128 + ((lane >> 4) * 8) * 2);
    const uint32_t bU = (uint32_t)((wN * 32 + (lane & 7) + ((lane >> 4) << 3)) * 128
                                   + (((lane >> 3) & 1) * 8) * 2);

    float acc[2][4][4];
#pragma unroll
    for (int mt = 0; mt < 2; ++mt)
#pragma unroll
        for (int nt = 0; nt < 4; ++nt)
#pragma unroll
            for (int e = 0; e < 4; ++e) acc[mt][nt][e] = 0.0f;

    // ---- chunk loader: 1024 uint2 per matrix, 512 threads -> 2 iters ----
    auto load_chunk = [&](int chunk, uint32_t stg) {
        const int k0 = chunk * KC;
#pragma unroll
        for (int it = 0; it < 2; ++it) {
            int li = it * NTHREADS + tid;
            int r = li >> 3, c16 = li & 7;
            uint32_t soff = swz((uint32_t)(r * 128 + c16 * 16));
            size_t aoff = (size_t)(m0 + r) * HID + k0 + c16 * 8;
            cp16(stg + TO_AHI + soff, g_hhi + aoff);
            cp16(stg + TO_ALO + soff, g_hlo + aoff);
            size_t boff = (size_t)((r >> 5) * HID + j0 + (r & 31)) * HID + k0 + c16 * 8;
            cp16(stg + TO_BHI + soff, g_Whi + boff);
            cp16(stg + TO_BLO + soff, g_Wlo + boff);
        }
    };
    // ---- chunk compute ----
    auto compute_chunk = [&](uint32_t stg) {
#pragma unroll
        for (int k16 = 0; k16 < 4; ++k16) {
            const uint32_t ko = (uint32_t)k16 * 32;   // 16 bf16 = 32 bytes along K
            uint32_t aHi[2][4], aLo[2][4];
#pragma unroll
            for (int mt = 0; mt < 2; ++mt) {
                uint32_t so = swz(aU + (uint32_t)mt * 2048 + ko);
                ldsm4(aHi[mt], stg + TO_AHI + so);
                ldsm4(aLo[mt], stg + TO_ALO + so);
            }
            uint32_t bH[4][2], bL[4][2];
#pragma unroll
            for (int half = 0; half < 2; ++half) {
                uint32_t so = swz(bU + (uint32_t)half * 2048 + ko);
                uint32_t t[4];
                ldsm4(t, stg + TO_BHI + so);        // non-trans: B stored [N][K], K contiguous
                bH[half*2][0] = t[0]; bH[half*2][1] = t[1];
                bH[half*2+1][0] = t[2]; bH[half*2+1][1] = t[3];
                ldsm4(t, stg + TO_BLO + so);
                bL[half*2][0] = t[0]; bL[half*2][1] = t[1];
                bL[half*2+1][0] = t[2]; bL[half*2+1][1] = t[3];
            }
#pragma unroll
            for (int mt = 0; mt < 2; ++mt)
#pragma unroll
                for (int nt = 0; nt < 4; ++nt) {
                    hmma(acc[mt][nt], aHi[mt], bH[nt]);
                    hmma(acc[mt][nt], aHi[mt], bL[nt]);
                    hmma(acc[mt][nt], aLo[mt], bH[nt]);
                }
        }
    };

    const uint32_t stg0 = sb + SO_STAGE;
    // prime pipeline: chunks 0,1
    load_chunk(0, stg0);
    asm volatile("cp.async.commit_group;");
    load_chunk(1, stg0 + STAGE_BYTES);
    asm volatile("cp.async.commit_group;");

    for (int i = 0; i < NCHUNK; ++i) {
        if (i + 2 < NCHUNK) {
            load_chunk(i + 2, stg0 + ((i + 2) % 3) * STAGE_BYTES);
            asm volatile("cp.async.commit_group;");
            asm volatile("cp.async.wait_group 2;");
        } else if (i + 2 == NCHUNK) {
            asm volatile("cp.async.wait_group 1;");
        } else {
            asm volatile("cp.async.wait_group 0;");
        }
        __syncthreads();
        compute_chunk(stg0 + (i % 3) * STAGE_BYTES);
        __syncthreads();
    }

    // ---- accumulators -> gate buffer (f32) ----
#pragma unroll
    for (int mt = 0; mt < 2; ++mt)
#pragma unroll
        for (int nt = 0; nt < 4; ++nt) {
            int row = wM * 32 + mt * 16 + (lane >> 2);
            int col = wN * 32 + nt * 8 + (lane & 3) * 2;
            gbuf[row * GBUF_LD + col]           = acc[mt][nt][0];
            gbuf[row * GBUF_LD + col + 1]       = acc[mt][nt][1];
            gbuf[(row + 8) * GBUF_LD + col]     = acc[mt][nt][2];
            gbuf[(row + 8) * GBUF_LD + col + 1] = acc[mt][nt][3];
        }
    __syncthreads();

    // ---- cell update + fused readout partials (4096 elems, 512 threads) ----
#pragma unroll
    for (int it = 0; it < 8; ++it) {
        int li = it * NTHREADS + tid;
        int b  = li >> 5;          // same for all lanes of a warp
        int jj = li & 31;          // = lane

        float xv = s_x[b];
        float gi = gbuf[b * GBUF_LD +      jj] + xv * s_wih[jj]      + s_bsum[jj];
        float gf = gbuf[b * GBUF_LD + 32 + jj] + xv * s_wih[32 + jj] + s_bsum[32 + jj];
        float gg = gbuf[b * GBUF_LD + 64 + jj] + xv * s_wih[64 + jj] + s_bsum[64 + jj];
        float go = gbuf[b * GBUF_LD + 96 + jj] + xv * s_wih[96 + jj] + s_bsum[96 + jj];

        size_t idx = (size_t)(m0 + b) * HID + j0 + jj;
        float c_old = g_c[idx];
        float c_new = sigf(gf) * c_old + sigf(gi) * tanhf(gg);
        float h_new = sigf(go) * tanhf(c_new);

        g_c[idx] = c_new;
        __nv_bfloat16 hi = __float2bfloat16(h_new);
        g_hhi[idx] = hi;
        g_hlo[idx] = __float2bfloat16(h_new - __bfloat162float(hi));

        // readout partial: sum over this CTA's 32 hidden cols
        float p = h_new * s_wout[jj];
#pragma unroll
        for (int off = 16; off > 0; off >>= 1) p += __shfl_xor_sync(0xFFFFFFFFu, p, off);
        if (lane == 0) g_parts[blockIdx.y * BATCH + m0 + b] = p;
    }
}

// ---------------- final prediction (last step's readout) ----------------
__global__ void pred_final(const float* __restrict__ b_out, float* __restrict__ out, int steps) {
    int b = blockIdx.x * blockDim.x + threadIdx.x;
    if (b < BATCH) {
        float acc = 0.0f;
#pragma unroll 8
        for (int p = 0; p < 32; ++p) acc += g_parts[p * BATCH + b];
        out[(size_t)b * steps + (steps - 1)] = acc + b_out[0];
    }
}

// ---------------- launch ----------------
extern "C" void kernel_launch(void* const* d_in, const int* in_sizes, int n_in,
                              void* d_out, int out_size) {
    const float* data  = (const float*)d_in[0];  // [B, T, 1]
    const float* W_ih  = (const float*)d_in[1];  // [4H, 1]
    const float* W_hh  = (const float*)d_in[2];  // [4H, H]
    const float* b_ih  = (const float*)d_in[3];
    const float* b_hh  = (const float*)d_in[4];
    const float* W_out = (const float*)d_in[5];  // [1, H]
    const float* b_out = (const float*)d_in[6];
    float* out = (float*)d_out;                  // [B, STEPS, 1]

    int T     = in_sizes[0] / BATCH;   // 64
    int steps = out_size / BATCH;      // 96

    cudaFuncSetAttribute(lstm_step, cudaFuncAttributeMaxDynamicSharedMemorySize, SMEM_TOTAL);

    prep_split_kernel<<<2048, 512>>>(W_hh);
    init_zero_kernel<<<512, 512>>>();

    dim3 grid(BATCH / TILEM, HID / NH);   // (4, 32)

    // warmup over the input sequence
    for (int t = 0; t < T; ++t)
        lstm_step<<<grid, NTHREADS, SMEM_TOTAL>>>(0, data + t, T, 0, steps,
                                                  W_ih, b_ih, b_hh, W_out, b_out, out);
    // autoregressive decode: step s consumes pred_{s-1} (parts) and writes out[:, s-1]
    for (int s = 1; s < steps; ++s)
        lstm_step<<<grid, NTHREADS, SMEM_TOTAL>>>(1, nullptr, 0, s - 1, steps,
                                                  W_ih, b_ih, b_hh, W_out, b_out, out);
    // final readout out[:, steps-1]
    pred_final<<<(BATCH + 255) / 256, 256>>>(b_out, out, steps);
}

// round 8
// speedup vs baseline: 2.4723x; 1.3834x over previous
#include <cuda_runtime.h>
#include <cuda_bf16.h>
#include <cstdint>
#include <math.h>

#define BATCH 512
#define HID   1024
#define GATES 4096
#define TILEM 128          // batch rows per CTA
#define NH    32           // hidden units per CTA (-> 128 gate cols)
#define KC    64           // K chunk (bf16 elems), 128B rows
#define NCHUNK (HID / KC)  // 16
#define NSTAGE 4
#define NTHREADS 512       // 16 warps, warp tile 32x32

// ---- shared memory layout (bytes) ----
#define SO_X      0         // 128 f32
#define SO_WIH    512       // 128 f32
#define SO_BSUM   1024      // 128 f32
#define SO_WOUT   1536      // 32 f32
#define SO_STAGE  2048
#define STAGE_BYTES 49152   // 3 matrices x 128 x 64 bf16 (16KB each)
#define TO_AHI    0
#define TO_BHI    16384
#define TO_BLO    32768
#define SMEM_TOTAL (SO_STAGE + NSTAGE * STAGE_BYTES)   // 198656
#define GBUF_LD   132       // f32 stride of gate buffer (reuses stage mem)

// ---------------- device scratch ----------------
__device__ __align__(128) float          g_c   [BATCH * HID];
__device__ __align__(128) __nv_bfloat16  g_hhi [BATCH * HID];
__device__ __align__(128) __nv_bfloat16  g_Whi [GATES * HID];
__device__ __align__(128) __nv_bfloat16  g_Wlo [GATES * HID];
__device__ __align__(128) float          g_parts[32 * BATCH];

// ---------------- helpers ----------------
__device__ __forceinline__ uint32_t smem_u32(const void* p) {
    uint32_t a;
    asm("{ .reg .u64 t; cvta.to.shared.u64 t, %1; cvt.u32.u64 %0, t; }" : "=r"(a) : "l"(p));
    return a;
}
__device__ __forceinline__ void cp16(uint32_t dst, const void* src) {
    asm volatile("cp.async.cg.shared.global [%0], [%1], 16;"
                 :: "r"(dst), "l"(__cvta_generic_to_global(src)));
}
__device__ __forceinline__ uint32_t swz(uint32_t off) { return off ^ ((off >> 3) & 0x70); }

__device__ __forceinline__ void ldsm4(uint32_t* r, uint32_t a) {
    asm volatile("ldmatrix.sync.aligned.m8n8.x4.shared.b16 {%0,%1,%2,%3}, [%4];"
                 : "=r"(r[0]), "=r"(r[1]), "=r"(r[2]), "=r"(r[3]) : "r"(a));
}
__device__ __forceinline__ void hmma(float* c, const uint32_t* a, const uint32_t* b) {
    asm volatile("mma.sync.aligned.m16n8k16.row.col.f32.bf16.bf16.f32 "
                 "{%0,%1,%2,%3}, {%4,%5,%6,%7}, {%8,%9}, {%0,%1,%2,%3};"
                 : "+f"(c[0]), "+f"(c[1]), "+f"(c[2]), "+f"(c[3])
                 : "r"(a[0]), "r"(a[1]), "r"(a[2]), "r"(a[3]), "r"(b[0]), "r"(b[1]));
}
__device__ __forceinline__ float sigf(float x) { return 1.0f / (1.0f + expf(-x)); }

// ---------------- prep / init ----------------
__global__ void prep_split_kernel(const float* __restrict__ W) {
    int n = GATES * HID;
    for (int i = blockIdx.x * blockDim.x + threadIdx.x; i < n; i += gridDim.x * blockDim.x) {
        float w = W[i];
        __nv_bfloat16 hi = __float2bfloat16(w);
        g_Whi[i] = hi;
        g_Wlo[i] = __float2bfloat16(w - __bfloat162float(hi));
    }
}
__global__ void init_zero_kernel() {
    int n = BATCH * HID;
    __nv_bfloat16 z = __float2bfloat16(0.0f);
    for (int i = blockIdx.x * blockDim.x + threadIdx.x; i < n; i += gridDim.x * blockDim.x) {
        g_c[i] = 0.0f; g_hhi[i] = z;
    }
}

// ---------------- one LSTM step (mma.sync pipeline, 2-term split) ----------------
// grid (4, 32), block 512 (16 warps, warp tile 32x32).
__global__ void __launch_bounds__(NTHREADS, 1)
lstm_step(int mode, const float* __restrict__ x, int xstride, int sprev, int steps,
          const float* __restrict__ W_ih, const float* __restrict__ b_ih,
          const float* __restrict__ b_hh, const float* __restrict__ W_out,
          const float* __restrict__ b_out, float* __restrict__ out)
{
    extern __shared__ __align__(1024) char sm[];
    const uint32_t sb = smem_u32(sm);
    const int tid  = threadIdx.x;
    const int wid  = tid >> 5;
    const int lane = tid & 31;
    const int m0 = blockIdx.x * TILEM;
    const int j0 = blockIdx.y * NH;
    const int wM = wid & 3;        // 0..3 -> 32-row slab
    const int wN = wid >> 2;       // 0..3 -> 32-col slab

    float* s_x    = (float*)(sm + SO_X);
    float* s_wih  = (float*)(sm + SO_WIH);
    float* s_bsum = (float*)(sm + SO_BSUM);
    float* s_wout = (float*)(sm + SO_WOUT);
    float* gbuf   = (float*)(sm + SO_STAGE);   // reused after mainloop

    // ---- prologue: x / wih / biases / wout into SMEM ----
    if (tid < 128) {
        int r = tid;
        float xv;
        if (mode == 0) {
            xv = x[(size_t)(m0 + r) * xstride];
        } else {
            float acc = 0.0f;
#pragma unroll 8
            for (int p = 0; p < 32; ++p) acc += g_parts[p * BATCH + m0 + r];
            xv = acc + b_out[0];
            if (blockIdx.y == 0) out[(size_t)(m0 + r) * steps + sprev] = xv;
        }
        s_x[r] = xv;
        int g = tid >> 5, jj = tid & 31;
        int j = g * HID + j0 + jj;
        s_wih[tid]  = W_ih[j];
        s_bsum[tid] = b_ih[j] + b_hh[j];
    } else if (tid < 160) {
        s_wout[tid - 128] = W_out[j0 + tid - 128];
    }

    // per-thread ldmatrix UNSWIZZLED base offsets (swizzle applied per-access)
    const uint32_t aU = (uint32_t)((wM * 32 + (lane & 15)) * 128 + ((lane >> 4) * 8) * 2);
    const uint32_t bU = (uint32_t)((wN * 32 + (lane & 7) + ((lane >> 4) << 3)) * 128
                                   + (((lane >> 3) & 1) * 8) * 2);

    float acc[2][4][4];
#pragma unroll
    for (int mt = 0; mt < 2; ++mt)
#pragma unroll
        for (int nt = 0; nt < 4; ++nt)
#pragma unroll
            for (int e = 0; e < 4; ++e) acc[mt][nt][e] = 0.0f;

    // ---- chunk loader: 3 matrices x 1024 uint2, 512 threads -> 2 iters ----
    auto load_chunk = [&](int chunk, uint32_t stg) {
        const int k0 = chunk * KC;
#pragma unroll
        for (int it = 0; it < 2; ++it) {
            int li = it * NTHREADS + tid;
            int r = li >> 3, c16 = li & 7;
            uint32_t soff = swz((uint32_t)(r * 128 + c16 * 16));
            size_t aoff = (size_t)(m0 + r) * HID + k0 + c16 * 8;
            cp16(stg + TO_AHI + soff, g_hhi + aoff);
            size_t boff = (size_t)((r >> 5) * HID + j0 + (r & 31)) * HID + k0 + c16 * 8;
            cp16(stg + TO_BHI + soff, g_Whi + boff);
            cp16(stg + TO_BLO + soff, g_Wlo + boff);
        }
    };
    // ---- chunk compute (2 terms: aHi*bHi + aHi*bLo) ----
    auto compute_chunk = [&](uint32_t stg) {
#pragma unroll
        for (int k16 = 0; k16 < 4; ++k16) {
            const uint32_t ko = (uint32_t)k16 * 32;   // 16 bf16 = 32 bytes along K
            uint32_t aHi[2][4];
#pragma unroll
            for (int mt = 0; mt < 2; ++mt) {
                uint32_t so = swz(aU + (uint32_t)mt * 2048 + ko);
                ldsm4(aHi[mt], stg + TO_AHI + so);
            }
            uint32_t bH[4][2], bL[4][2];
#pragma unroll
            for (int half = 0; half < 2; ++half) {
                uint32_t so = swz(bU + (uint32_t)half * 2048 + ko);
                uint32_t t[4];
                ldsm4(t, stg + TO_BHI + so);        // non-trans: B stored [N][K], K contiguous
                bH[half*2][0] = t[0]; bH[half*2][1] = t[1];
                bH[half*2+1][0] = t[2]; bH[half*2+1][1] = t[3];
                ldsm4(t, stg + TO_BLO + so);
                bL[half*2][0] = t[0]; bL[half*2][1] = t[1];
                bL[half*2+1][0] = t[2]; bL[half*2+1][1] = t[3];
            }
#pragma unroll
            for (int mt = 0; mt < 2; ++mt)
#pragma unroll
                for (int nt = 0; nt < 4; ++nt) {
                    hmma(acc[mt][nt], aHi[mt], bH[nt]);
                    hmma(acc[mt][nt], aHi[mt], bL[nt]);
                }
        }
    };

    const uint32_t stg0 = sb + SO_STAGE;
    // prime pipeline: chunks 0..2
    load_chunk(0, stg0 + 0 * STAGE_BYTES);
    asm volatile("cp.async.commit_group;");
    load_chunk(1, stg0 + 1 * STAGE_BYTES);
    asm volatile("cp.async.commit_group;");
    load_chunk(2, stg0 + 2 * STAGE_BYTES);
    asm volatile("cp.async.commit_group;");

    // single __syncthreads per chunk: load(i+3) targets stage (i-1)%4, whose
    // compute finished before this iteration's barrier.
#pragma unroll 1
    for (int i = 0; i < NCHUNK; ++i) {
        if (i < NCHUNK - 2)      asm volatile("cp.async.wait_group 2;");
        else if (i == NCHUNK - 2) asm volatile("cp.async.wait_group 1;");
        else                      asm volatile("cp.async.wait_group 0;");
        __syncthreads();
        compute_chunk(stg0 + (i & 3) * STAGE_BYTES);
        if (i + 3 < NCHUNK) {
            load_chunk(i + 3, stg0 + ((i + 3) & 3) * STAGE_BYTES);
            asm volatile("cp.async.commit_group;");
        }
    }
    __syncthreads();

    // ---- accumulators -> gate buffer (f32) ----
#pragma unroll
    for (int mt = 0; mt < 2; ++mt)
#pragma unroll
        for (int nt = 0; nt < 4; ++nt) {
            int row = wM * 32 + mt * 16 + (lane >> 2);
            int col = wN * 32 + nt * 8 + (lane & 3) * 2;
            gbuf[row * GBUF_LD + col]           = acc[mt][nt][0];
            gbuf[row * GBUF_LD + col + 1]       = acc[mt][nt][1];
            gbuf[(row + 8) * GBUF_LD + col]     = acc[mt][nt][2];
            gbuf[(row + 8) * GBUF_LD + col + 1] = acc[mt][nt][3];
        }
    __syncthreads();

    // ---- cell update + fused readout partials (4096 elems, 512 threads) ----
#pragma unroll
    for (int it = 0; it < 8; ++it) {
        int li = it * NTHREADS + tid;
        int b  = li >> 5;          // same for all lanes of a warp
        int jj = li & 31;          // = lane

        float xv = s_x[b];
        float gi = gbuf[b * GBUF_LD +      jj] + xv * s_wih[jj]      + s_bsum[jj];
        float gf = gbuf[b * GBUF_LD + 32 + jj] + xv * s_wih[32 + jj] + s_bsum[32 + jj];
        float gg = gbuf[b * GBUF_LD + 64 + jj] + xv * s_wih[64 + jj] + s_bsum[64 + jj];
        float go = gbuf[b * GBUF_LD + 96 + jj] + xv * s_wih[96 + jj] + s_bsum[96 + jj];

        size_t idx = (size_t)(m0 + b) * HID + j0 + jj;
        float c_old = g_c[idx];
        float c_new = sigf(gf) * c_old + sigf(gi) * tanhf(gg);
        float h_new = sigf(go) * tanhf(c_new);

        g_c[idx] = c_new;
        g_hhi[idx] = __float2bfloat16(h_new);

        // readout partial: sum over this CTA's 32 hidden cols (exact h)
        float p = h_new * s_wout[jj];
#pragma unroll
        for (int off = 16; off > 0; off >>= 1) p += __shfl_xor_sync(0xFFFFFFFFu, p, off);
        if (lane == 0) g_parts[blockIdx.y * BATCH + m0 + b] = p;
    }
}

// ---------------- final prediction (last step's readout) ----------------
__global__ void pred_final(const float* __restrict__ b_out, float* __restrict__ out, int steps) {
    int b = blockIdx.x * blockDim.x + threadIdx.x;
    if (b < BATCH) {
        float acc = 0.0f;
#pragma unroll 8
        for (int p = 0; p < 32; ++p) acc += g_parts[p * BATCH + b];
        out[(size_t)b * steps + (steps - 1)] = acc + b_out[0];
    }
}

// ---------------- launch ----------------
extern "C" void kernel_launch(void* const* d_in, const int* in_sizes, int n_in,
                              void* d_out, int out_size) {
    const float* data  = (const float*)d_in[0];  // [B, T, 1]
    const float* W_ih  = (const float*)d_in[1];  // [4H, 1]
    const float* W_hh  = (const float*)d_in[2];  // [4H, H]
    const float* b_ih  = (const float*)d_in[3];
    const float* b_hh  = (const float*)d_in[4];
    const float* W_out = (const float*)d_in[5];  // [1, H]
    const float* b_out = (const float*)d_in[6];
    float* out = (float*)d_out;                  // [B, STEPS, 1]

    int T     = in_sizes[0] / BATCH;   // 64
    int steps = out_size / BATCH;      // 96

    cudaFuncSetAttribute(lstm_step, cudaFuncAttributeMaxDynamicSharedMemorySize, SMEM_TOTAL);

    prep_split_kernel<<<2048, 512>>>(W_hh);
    init_zero_kernel<<<512, 512>>>();

    dim3 grid(BATCH / TILEM, HID / NH);   // (4, 32)

    // warmup over the input sequence
    for (int t = 0; t < T; ++t)
        lstm_step<<<grid, NTHREADS, SMEM_TOTAL>>>(0, data + t, T, 0, steps,
                                                  W_ih, b_ih, b_hh, W_out, b_out, out);
    // autoregressive decode: step s consumes pred_{s-1} (parts) and writes out[:, s-1]
    for (int s = 1; s < steps; ++s)
        lstm_step<<<grid, NTHREADS, SMEM_TOTAL>>>(1, nullptr, 0, s - 1, steps,
                                                  W_ih, b_ih, b_hh, W_out, b_out, out);
    // final readout out[:, steps-1]
    pred_final<<<(BATCH + 255) / 256, 256>>>(b_out, out, steps);
}

// round 9
// speedup vs baseline: 2.5288x; 1.0229x over previous
#include <cuda_runtime.h>
#include <cuda_bf16.h>
#include <cstdint>
#include <math.h>

#define BATCH 512
#define HID   1024
#define GATES 4096
#define TILEM 128          // batch rows per CTA
#define NH    32           // hidden units per CTA (-> 128 gate cols)
#define KC    64           // K chunk (bf16 elems), 128B rows
#define NCHUNK (HID / KC)  // 16
#define NSTAGE 4
#define NTHREADS 512       // 16 warps, warp tile 32x32
#define NCTA  128          // (BATCH/TILEM) * (HID/NH)

// ---- shared memory layout (bytes) ----
#define SO_X      0         // 128 f32
#define SO_WIH    512       // 128 f32
#define SO_BSUM   1024      // 128 f32
#define SO_WOUT   1536      // 32 f32
#define SO_C      1664      // 128*33 f32 = 16896 (persistent cell state)
#define SO_STAGE  19456     // 1024-aligned
#define STAGE_BYTES 49152   // 3 matrices x 128 x 64 bf16 (16KB each)
#define TO_AHI    0
#define TO_BHI    16384
#define TO_BLO    32768
#define SMEM_TOTAL (SO_STAGE + NSTAGE * STAGE_BYTES)   // 216064
#define GBUF_LD   132       // f32 stride of gate buffer (reuses stage mem)

// ---------------- device scratch ----------------
__device__ __align__(128) __nv_bfloat16  g_hh  [2][BATCH * HID];   // double-buffered h (bf16)
__device__ __align__(128) __nv_bfloat16  g_Whi [GATES * HID];
__device__ __align__(128) __nv_bfloat16  g_Wlo [GATES * HID];
__device__ __align__(128) float          g_parts[2][32 * BATCH];   // double-buffered readout partials
__device__ unsigned g_bar;

// ---------------- helpers ----------------
__device__ __forceinline__ uint32_t smem_u32(const void* p) {
    uint32_t a;
    asm("{ .reg .u64 t; cvta.to.shared.u64 t, %1; cvt.u32.u64 %0, t; }" : "=r"(a) : "l"(p));
    return a;
}
__device__ __forceinline__ void cp16(uint32_t dst, const void* src) {
    asm volatile("cp.async.cg.shared.global [%0], [%1], 16;"
                 :: "r"(dst), "l"(__cvta_generic_to_global(src)));
}
__device__ __forceinline__ uint32_t swz(uint32_t off) { return off ^ ((off >> 3) & 0x70); }

__device__ __forceinline__ void ldsm4(uint32_t* r, uint32_t a) {
    asm volatile("ldmatrix.sync.aligned.m8n8.x4.shared.b16 {%0,%1,%2,%3}, [%4];"
                 : "=r"(r[0]), "=r"(r[1]), "=r"(r[2]), "=r"(r[3]) : "r"(a));
}
__device__ __forceinline__ void hmma(float* c, const uint32_t* a, const uint32_t* b) {
    asm volatile("mma.sync.aligned.m16n8k16.row.col.f32.bf16.bf16.f32 "
                 "{%0,%1,%2,%3}, {%4,%5,%6,%7}, {%8,%9}, {%0,%1,%2,%3};"
                 : "+f"(c[0]), "+f"(c[1]), "+f"(c[2]), "+f"(c[3])
                 : "r"(a[0]), "r"(a[1]), "r"(a[2]), "r"(a[3]), "r"(b[0]), "r"(b[1]));
}
// fast, overflow-safe transcendentals (err ~1e-6 rel, far below budget)
__device__ __forceinline__ float sigf(float x) {
    return __fdividef(1.0f, 1.0f + __expf(-x));
}
__device__ __forceinline__ float tanhf_fast(float x) {
    float ax = fabsf(x);
    float e  = __expf(-2.0f * ax);
    float t  = __fdividef(1.0f - e, 1.0f + e);
    return copysignf(t, x);
}

// ---------------- prep / init ----------------
__global__ void prep_split_kernel(const float* __restrict__ W) {
    int n = GATES * HID;
    for (int i = blockIdx.x * blockDim.x + threadIdx.x; i < n; i += gridDim.x * blockDim.x) {
        float w = W[i];
        __nv_bfloat16 hi = __float2bfloat16(w);
        g_Whi[i] = hi;
        g_Wlo[i] = __float2bfloat16(w - __bfloat162float(hi));
    }
}
__global__ void init_zero_kernel() {
    int n = BATCH * HID;
    __nv_bfloat16 z = __float2bfloat16(0.0f);
    for (int i = blockIdx.x * blockDim.x + threadIdx.x; i < n; i += gridDim.x * blockDim.x) {
        g_hh[0][i] = z; g_hh[1][i] = z;
    }
    if (blockIdx.x == 0 && threadIdx.x == 0) g_bar = 0u;
}

// ---------------- persistent LSTM kernel ----------------
// grid 128 (= 4 m-tiles x 32 j-tiles), block 512 (16 warps, warp tile 32x32).
__global__ void __launch_bounds__(NTHREADS, 1)
lstm_persist(const float* __restrict__ data, const float* __restrict__ W_ih,
             const float* __restrict__ b_ih, const float* __restrict__ b_hh,
             const float* __restrict__ W_out, const float* __restrict__ b_out,
             float* __restrict__ out, int T, int steps)
{
    extern __shared__ __align__(1024) char sm[];
    const uint32_t sb = smem_u32(sm);
    const int tid  = threadIdx.x;
    const int wid  = tid >> 5;
    const int lane = tid & 31;
    const int mb = blockIdx.x & 3;
    const int jb = blockIdx.x >> 2;
    const int m0 = mb * TILEM;
    const int j0 = jb * NH;
    const int wM = wid & 3;        // 0..3 -> 32-row slab
    const int wN = wid >> 2;       // 0..3 -> 32-col slab

    float* s_x    = (float*)(sm + SO_X);
    float* s_wih  = (float*)(sm + SO_WIH);
    float* s_bsum = (float*)(sm + SO_BSUM);
    float* s_wout = (float*)(sm + SO_WOUT);
    float* s_c    = (float*)(sm + SO_C);       // persistent cell state [128][33]
    float* gbuf   = (float*)(sm + SO_STAGE);   // reused after each mainloop

    // ---- one-time prologue: constants into SMEM, zero c ----
    if (tid < 128) {
        int g = tid >> 5, jj = tid & 31;
        int j = g * HID + j0 + jj;
        s_wih[tid]  = W_ih[j];
        s_bsum[tid] = b_ih[j] + b_hh[j];
    } else if (tid < 160) {
        s_wout[tid - 128] = W_out[j0 + tid - 128];
    }
    for (int li = tid; li < 128 * 33; li += NTHREADS) s_c[li] = 0.0f;
    const float bout = b_out[0];

    // per-thread ldmatrix UNSWIZZLED base offsets (swizzle applied per-access)
    const uint32_t aU = (uint32_t)((wM * 32 + (lane & 15)) * 128 + ((lane >> 4) * 8) * 2);
    const uint32_t bU = (uint32_t)((wN * 32 + (lane & 7) + ((lane >> 4) << 3)) * 128
                                   + (((lane >> 3) & 1) * 8) * 2);
    const uint32_t stg0 = sb + SO_STAGE;

    const int total = T + steps - 1;   // 159 cell steps
    unsigned bar_target = 0;
    __syncthreads();

    for (int g = 0; g < total; ++g) {
        const int rbuf = (g & 1) ^ 1;       // h/parts written at step g-1
        const int wbuf = g & 1;
        const __nv_bfloat16* hsrc = g_hh[rbuf];

        // ---- per-step prologue: x into SMEM (+ out write for AR steps) ----
        if (tid < 128) {
            float xv;
            if (g < T) {
                xv = data[(size_t)(m0 + tid) * T + g];
            } else {
                float acc = 0.0f;
#pragma unroll 8
                for (int p = 0; p < 32; ++p)
                    acc += __ldcg(&g_parts[rbuf][p * BATCH + m0 + tid]);
                xv = acc + bout;
                if (jb == 0) out[(size_t)(m0 + tid) * steps + (g - T)] = xv;
            }
            s_x[tid] = xv;
        }

        // ---- chunk loader ----
        auto load_chunk = [&](int chunk, uint32_t stg) {
            const int k0 = chunk * KC;
#pragma unroll
            for (int it = 0; it < 2; ++it) {
                int li = it * NTHREADS + tid;
                int r = li >> 3, c16 = li & 7;
                uint32_t soff = swz((uint32_t)(r * 128 + c16 * 16));
                size_t aoff = (size_t)(m0 + r) * HID + k0 + c16 * 8;
                cp16(stg + TO_AHI + soff, hsrc + aoff);
                size_t boff = (size_t)((r >> 5) * HID + j0 + (r & 31)) * HID + k0 + c16 * 8;
                cp16(stg + TO_BHI + soff, g_Whi + boff);
                cp16(stg + TO_BLO + soff, g_Wlo + boff);
            }
        };

        float acc[2][4][4];
#pragma unroll
        for (int mt = 0; mt < 2; ++mt)
#pragma unroll
            for (int nt = 0; nt < 4; ++nt)
#pragma unroll
                for (int e = 0; e < 4; ++e) acc[mt][nt][e] = 0.0f;

        // prime pipeline: chunks 0..2
        load_chunk(0, stg0 + 0 * STAGE_BYTES);
        asm volatile("cp.async.commit_group;");
        load_chunk(1, stg0 + 1 * STAGE_BYTES);
        asm volatile("cp.async.commit_group;");
        load_chunk(2, stg0 + 2 * STAGE_BYTES);
        asm volatile("cp.async.commit_group;");

#pragma unroll 1
        for (int i = 0; i < NCHUNK; ++i) {
            if (i < NCHUNK - 2)       asm volatile("cp.async.wait_group 2;");
            else if (i == NCHUNK - 2) asm volatile("cp.async.wait_group 1;");
            else                      asm volatile("cp.async.wait_group 0;");
            __syncthreads();
            // compute chunk i
            {
                const uint32_t stg = stg0 + (i & 3) * STAGE_BYTES;
#pragma unroll
                for (int k16 = 0; k16 < 4; ++k16) {
                    const uint32_t ko = (uint32_t)k16 * 32;
                    uint32_t aHi[2][4];
#pragma unroll
                    for (int mt = 0; mt < 2; ++mt) {
                        uint32_t so = swz(aU + (uint32_t)mt * 2048 + ko);
                        ldsm4(aHi[mt], stg + TO_AHI + so);
                    }
                    uint32_t bH[4][2], bL[4][2];
#pragma unroll
                    for (int half = 0; half < 2; ++half) {
                        uint32_t so = swz(bU + (uint32_t)half * 2048 + ko);
                        uint32_t t[4];
                        ldsm4(t, stg + TO_BHI + so);
                        bH[half*2][0] = t[0]; bH[half*2][1] = t[1];
                        bH[half*2+1][0] = t[2]; bH[half*2+1][1] = t[3];
                        ldsm4(t, stg + TO_BLO + so);
                        bL[half*2][0] = t[0]; bL[half*2][1] = t[1];
                        bL[half*2+1][0] = t[2]; bL[half*2+1][1] = t[3];
                    }
#pragma unroll
                    for (int mt = 0; mt < 2; ++mt)
#pragma unroll
                        for (int nt = 0; nt < 4; ++nt) {
                            hmma(acc[mt][nt], aHi[mt], bH[nt]);
                            hmma(acc[mt][nt], aHi[mt], bL[nt]);
                        }
                }
            }
            if (i + 3 < NCHUNK) {
                load_chunk(i + 3, stg0 + ((i + 3) & 3) * STAGE_BYTES);
                asm volatile("cp.async.commit_group;");
            }
        }
        __syncthreads();

        // ---- accumulators -> gate buffer (f32) ----
#pragma unroll
        for (int mt = 0; mt < 2; ++mt)
#pragma unroll
            for (int nt = 0; nt < 4; ++nt) {
                int row = wM * 32 + mt * 16 + (lane >> 2);
                int col = wN * 32 + nt * 8 + (lane & 3) * 2;
                gbuf[row * GBUF_LD + col]           = acc[mt][nt][0];
                gbuf[row * GBUF_LD + col + 1]       = acc[mt][nt][1];
                gbuf[(row + 8) * GBUF_LD + col]     = acc[mt][nt][2];
                gbuf[(row + 8) * GBUF_LD + col + 1] = acc[mt][nt][3];
            }
        __syncthreads();

        // ---- cell update + fused readout partials ----
#pragma unroll
        for (int it = 0; it < 8; ++it) {
            int li = it * NTHREADS + tid;
            int b  = li >> 5;
            int jj = li & 31;          // = lane

            float xv = s_x[b];
            float gi = gbuf[b * GBUF_LD +      jj] + xv * s_wih[jj]      + s_bsum[jj];
            float gf = gbuf[b * GBUF_LD + 32 + jj] + xv * s_wih[32 + jj] + s_bsum[32 + jj];
            float gg = gbuf[b * GBUF_LD + 64 + jj] + xv * s_wih[64 + jj] + s_bsum[64 + jj];
            float go = gbuf[b * GBUF_LD + 96 + jj] + xv * s_wih[96 + jj] + s_bsum[96 + jj];

            float c_old = s_c[b * 33 + jj];
            float c_new = sigf(gf) * c_old + sigf(gi) * tanhf_fast(gg);
            float h_new = sigf(go) * tanhf_fast(c_new);

            s_c[b * 33 + jj] = c_new;
            g_hh[wbuf][(size_t)(m0 + b) * HID + j0 + jj] = __float2bfloat16(h_new);

            float p = h_new * s_wout[jj];
#pragma unroll
            for (int off = 16; off > 0; off >>= 1) p += __shfl_xor_sync(0xFFFFFFFFu, p, off);
            if (lane == 0) g_parts[wbuf][jb * BATCH + m0 + b] = p;
        }

        // ---- grid barrier (protects h/parts buffers across steps) ----
        bar_target += NCTA;
        __threadfence();
        __syncthreads();
        if (tid == 0) {
            atomicAdd(&g_bar, 1u);
            while (*((volatile unsigned*)&g_bar) < bar_target) { __nanosleep(32); }
        }
        __syncthreads();
        __threadfence();
    }

    // ---- final prediction: out[:, steps-1] from last parts ----
    if (jb == 0 && tid < 128) {
        const int lbuf = (total - 1) & 1;
        float acc = 0.0f;
#pragma unroll 8
        for (int p = 0; p < 32; ++p)
            acc += __ldcg(&g_parts[lbuf][p * BATCH + m0 + tid]);
        out[(size_t)(m0 + tid) * steps + (steps - 1)] = acc + bout;
    }
}

// ---------------- launch ----------------
extern "C" void kernel_launch(void* const* d_in, const int* in_sizes, int n_in,
                              void* d_out, int out_size) {
    const float* data  = (const float*)d_in[0];  // [B, T, 1]
    const float* W_ih  = (const float*)d_in[1];  // [4H, 1]
    const float* W_hh  = (const float*)d_in[2];  // [4H, H]
    const float* b_ih  = (const float*)d_in[3];
    const float* b_hh  = (const float*)d_in[4];
    const float* W_out = (const float*)d_in[5];  // [1, H]
    const float* b_out = (const float*)d_in[6];
    float* out = (float*)d_out;                  // [B, STEPS, 1]

    int T     = in_sizes[0] / BATCH;   // 64
    int steps = out_size / BATCH;      // 96

    cudaFuncSetAttribute(lstm_persist, cudaFuncAttributeMaxDynamicSharedMemorySize, SMEM_TOTAL);

    prep_split_kernel<<<2048, 512>>>(W_hh);
    init_zero_kernel<<<512, 512>>>();

    lstm_persist<<<NCTA, NTHREADS, SMEM_TOTAL>>>(data, W_ih, b_ih, b_hh,
                                                 W_out, b_out, out, T, steps);
}

// round 10
// speedup vs baseline: 2.7945x; 1.1051x over previous
#include <cuda_runtime.h>
#include <cuda_bf16.h>
#include <cstdint>
#include <math.h>

#define BATCH 512
#define HID   1024
#define GATES 4096
#define TILEM 128          // batch rows per CTA
#define NH    32           // hidden units per CTA (-> 128 gate cols, gate-interleaved)
#define KC    64           // K chunk (bf16 elems), 128B rows
#define NCHUNK (HID / KC)  // 16
#define NTHREADS 512       // 16 warps, warp tile 32x32
#define NCTA  128          // (BATCH/TILEM) * (HID/NH)

// ---- shared memory layout (bytes) ----
#define SO_X      0         // 128 f32
#define SO_WOUT   512       // 32 f32
#define SO_PRED   640       // 4*128 f32
#define SO_STAGE  4096      // 1024-aligned
#define STAGE_BYTES 49152   // A(16KB) + Bhi(16KB) + Blo(16KB)
#define TO_AHI    0
#define TO_BHI    16384
#define TO_BLO    32768
#define SMEM_TOTAL (SO_STAGE + 4 * STAGE_BYTES)   // 200704

// column mapping within a CTA's 128 gate-cols: n -> gate=(n>>3)&3, hid=(n&7)+((n>>5)<<3)
// ---------------- device scratch ----------------
__device__ __align__(128) __nv_bfloat16  g_hh  [2][BATCH * HID];   // double-buffered h (bf16)
__device__ __align__(128) __nv_bfloat16  g_Whi [GATES * HID];
__device__ __align__(128) __nv_bfloat16  g_Wlo [GATES * HID];
__device__ __align__(128) float          g_parts[2][32 * BATCH];   // double-buffered readout partials
__device__ unsigned g_bar;

// ---------------- helpers ----------------
__device__ __forceinline__ uint32_t smem_u32(const void* p) {
    uint32_t a;
    asm("{ .reg .u64 t; cvta.to.shared.u64 t, %1; cvt.u32.u64 %0, t; }" : "=r"(a) : "l"(p));
    return a;
}
__device__ __forceinline__ void cp16(uint32_t dst, const void* src) {
    asm volatile("cp.async.cg.shared.global [%0], [%1], 16;"
                 :: "r"(dst), "l"(__cvta_generic_to_global(src)));
}
__device__ __forceinline__ uint32_t swz(uint32_t off) { return off ^ ((off >> 3) & 0x70); }

__device__ __forceinline__ void ldsm4(uint32_t* r, uint32_t a) {
    asm volatile("ldmatrix.sync.aligned.m8n8.x4.shared.b16 {%0,%1,%2,%3}, [%4];"
                 : "=r"(r[0]), "=r"(r[1]), "=r"(r[2]), "=r"(r[3]) : "r"(a));
}
__device__ __forceinline__ void hmma(float* c, const uint32_t* a, const uint32_t* b) {
    asm volatile("mma.sync.aligned.m16n8k16.row.col.f32.bf16.bf16.f32 "
                 "{%0,%1,%2,%3}, {%4,%5,%6,%7}, {%8,%9}, {%0,%1,%2,%3};"
                 : "+f"(c[0]), "+f"(c[1]), "+f"(c[2]), "+f"(c[3])
                 : "r"(a[0]), "r"(a[1]), "r"(a[2]), "r"(a[3]), "r"(b[0]), "r"(b[1]));
}
__device__ __forceinline__ float sigf(float x) {
    return __fdividef(1.0f, 1.0f + __expf(-x));
}
__device__ __forceinline__ float tanhf_fast(float x) {
    float ax = fabsf(x);
    float e  = __expf(-2.0f * ax);
    float t  = __fdividef(1.0f - e, 1.0f + e);
    return copysignf(t, x);
}

// ---------------- prep / init ----------------
__global__ void prep_split_kernel(const float* __restrict__ W) {
    int n = GATES * HID;
    for (int i = blockIdx.x * blockDim.x + threadIdx.x; i < n; i += gridDim.x * blockDim.x) {
        float w = W[i];
        __nv_bfloat16 hi = __float2bfloat16(w);
        g_Whi[i] = hi;
        g_Wlo[i] = __float2bfloat16(w - __bfloat162float(hi));
    }
}
__global__ void init_zero_kernel() {
    int n = BATCH * HID;
    __nv_bfloat16 z = __float2bfloat16(0.0f);
    for (int i = blockIdx.x * blockDim.x + threadIdx.x; i < n; i += gridDim.x * blockDim.x) {
        g_hh[0][i] = z; g_hh[1][i] = z;
    }
    if (blockIdx.x == 0 && threadIdx.x == 0) g_bar = 0u;
}

// ---------------- persistent LSTM kernel ----------------
__global__ void __launch_bounds__(NTHREADS, 1)
lstm_persist(const float* __restrict__ data, const float* __restrict__ W_ih,
             const float* __restrict__ b_ih, const float* __restrict__ b_hh,
             const float* __restrict__ W_out, const float* __restrict__ b_out,
             float* __restrict__ out, int T, int steps)
{
    extern __shared__ __align__(1024) char sm[];
    const uint32_t sb = smem_u32(sm);
    const int tid  = threadIdx.x;
    const int wid  = tid >> 5;
    const int lane = tid & 31;
    const int mb = blockIdx.x & 3;
    const int jb = blockIdx.x >> 2;
    const int m0 = mb * TILEM;
    const int j0 = jb * NH;
    const int wM = wid & 3;        // 0..3 -> 32-row slab
    const int wN = wid >> 2;       // 0..3 -> 32-col slab (8 hidden units x 4 gates)

    float* s_x    = (float*)(sm + SO_X);
    float* s_wout = (float*)(sm + SO_WOUT);
    float* s_pred = (float*)(sm + SO_PRED);

    // ---- one-time: per-thread gate weights/biases + wout, c state in regs ----
    const int hloc = wN * 8 + 2 * (lane & 3);   // local hidden base (2 units: hloc, hloc+1)
    float wih_r[4][2], bsum_r[4][2];
#pragma unroll
    for (int gt = 0; gt < 4; ++gt)
#pragma unroll
        for (int ej = 0; ej < 2; ++ej) {
            int j = gt * HID + j0 + hloc + ej;
            wih_r[gt][ej]  = W_ih[j];
            bsum_r[gt][ej] = b_ih[j] + b_hh[j];
        }
    if (tid < 32) s_wout[tid] = W_out[j0 + tid];
    const float bout = b_out[0];
    float c_reg[2][2][2];   // [mt][eh][ej]
#pragma unroll
    for (int a = 0; a < 2; ++a)
#pragma unroll
        for (int b = 0; b < 2; ++b)
#pragma unroll
            for (int d = 0; d < 2; ++d) c_reg[a][b][d] = 0.0f;

    // per-thread ldmatrix UNSWIZZLED base offsets
    const uint32_t aU = (uint32_t)((wM * 32 + (lane & 15)) * 128 + ((lane >> 4) * 8) * 2);
    const uint32_t bU = (uint32_t)((wN * 32 + (lane & 7) + ((lane >> 4) << 3)) * 128
                                   + (((lane >> 3) & 1) * 8) * 2);
    const uint32_t stg0 = sb + SO_STAGE;

    // ---- loaders ----
    // gate-interleaved B row r -> W row: gate=(r>>3)&3, hid=(r&7)+((r>>5)<<3)
    auto load_B = [&](int chunk, uint32_t stg) {
        const int k0 = chunk * KC;
#pragma unroll
        for (int it = 0; it < 2; ++it) {
            int li = it * NTHREADS + tid;
            int r = li >> 3, c16 = li & 7;
            uint32_t soff = swz((uint32_t)(r * 128 + c16 * 16));
            int wrow = ((r >> 3) & 3) * HID + j0 + (r & 7) + ((r >> 5) << 3);
            size_t boff = (size_t)wrow * HID + k0 + c16 * 8;
            cp16(stg + TO_BHI + soff, g_Whi + boff);
            cp16(stg + TO_BLO + soff, g_Wlo + boff);
        }
    };
    auto load_A = [&](const __nv_bfloat16* hsrc, int chunk, uint32_t stg) {
        const int k0 = chunk * KC;
#pragma unroll
        for (int it = 0; it < 2; ++it) {
            int li = it * NTHREADS + tid;
            int r = li >> 3, c16 = li & 7;
            uint32_t soff = swz((uint32_t)(r * 128 + c16 * 16));
            size_t aoff = (size_t)(m0 + r) * HID + k0 + c16 * 8;
            cp16(stg + TO_AHI + soff, hsrc + aoff);
        }
    };

    const int total = T + steps - 1;   // 159 cell steps
    unsigned bar_target = 0;
    __syncthreads();

    // prefetch B chunks 0..2 for the first step
    load_B(0, stg0 + 0 * STAGE_BYTES); asm volatile("cp.async.commit_group;");
    load_B(1, stg0 + 1 * STAGE_BYTES); asm volatile("cp.async.commit_group;");
    load_B(2, stg0 + 2 * STAGE_BYTES); asm volatile("cp.async.commit_group;");

    for (int g = 0; g < total; ++g) {
        const int rbuf = (g & 1) ^ 1;
        const int wbuf = g & 1;
        const __nv_bfloat16* hsrc = g_hh[rbuf];

        // ---- per-step prologue: x into SMEM (+ out write for AR steps) ----
        if (tid < 128) {
            float xv;
            if (g < T) {
                xv = data[(size_t)(m0 + tid) * T + g];
            } else {
                float acc2 = 0.0f;
#pragma unroll 8
                for (int p = 0; p < 32; ++p)
                    acc2 += __ldcg(&g_parts[rbuf][p * BATCH + m0 + tid]);
                xv = acc2 + bout;
                if (jb == 0) out[(size_t)(m0 + tid) * steps + (g - T)] = xv;
            }
            s_x[tid] = xv;
        }

        // ---- prime A chunks 0..2 (B already prefetched pre-barrier) ----
        load_A(hsrc, 0, stg0 + 0 * STAGE_BYTES); asm volatile("cp.async.commit_group;");
        load_A(hsrc, 1, stg0 + 1 * STAGE_BYTES); asm volatile("cp.async.commit_group;");
        load_A(hsrc, 2, stg0 + 2 * STAGE_BYTES); asm volatile("cp.async.commit_group;");

        float acc[2][4][4];
#pragma unroll
        for (int mt = 0; mt < 2; ++mt)
#pragma unroll
            for (int nt = 0; nt < 4; ++nt)
#pragma unroll
                for (int e = 0; e < 4; ++e) acc[mt][nt][e] = 0.0f;

#pragma unroll 1
        for (int i = 0; i < NCHUNK; ++i) {
            if (i < NCHUNK - 2)       asm volatile("cp.async.wait_group 2;");
            else if (i == NCHUNK - 2) asm volatile("cp.async.wait_group 1;");
            else                      asm volatile("cp.async.wait_group 0;");
            __syncthreads();
            {
                const uint32_t stg = stg0 + (i & 3) * STAGE_BYTES;
#pragma unroll
                for (int k16 = 0; k16 < 4; ++k16) {
                    const uint32_t ko = (uint32_t)k16 * 32;
                    uint32_t aHi[2][4];
#pragma unroll
                    for (int mt = 0; mt < 2; ++mt) {
                        uint32_t so = swz(aU + (uint32_t)mt * 2048 + ko);
                        ldsm4(aHi[mt], stg + TO_AHI + so);
                    }
                    uint32_t bH[4][2], bL[4][2];
#pragma unroll
                    for (int half = 0; half < 2; ++half) {
                        uint32_t so = swz(bU + (uint32_t)half * 2048 + ko);
                        uint32_t t[4];
                        ldsm4(t, stg + TO_BHI + so);
                        bH[half*2][0] = t[0]; bH[half*2][1] = t[1];
                        bH[half*2+1][0] = t[2]; bH[half*2+1][1] = t[3];
                        ldsm4(t, stg + TO_BLO + so);
                        bL[half*2][0] = t[0]; bL[half*2][1] = t[1];
                        bL[half*2+1][0] = t[2]; bL[half*2+1][1] = t[3];
                    }
#pragma unroll
                    for (int mt = 0; mt < 2; ++mt)
#pragma unroll
                        for (int nt = 0; nt < 4; ++nt) {
                            hmma(acc[mt][nt], aHi[mt], bH[nt]);
                            hmma(acc[mt][nt], aHi[mt], bL[nt]);
                        }
                }
            }
            if (i + 3 < NCHUNK) {
                uint32_t stg = stg0 + ((i + 3) & 3) * STAGE_BYTES;
                load_A(hsrc, i + 3, stg);
                load_B(i + 3, stg);
                asm volatile("cp.async.commit_group;");
            }
        }

        // ---- prefetch next step's B chunks 0..2 (overlaps epilogue + barrier) ----
        if (g + 1 < total) {
            load_B(0, stg0 + 0 * STAGE_BYTES); asm volatile("cp.async.commit_group;");
            load_B(1, stg0 + 1 * STAGE_BYTES); asm volatile("cp.async.commit_group;");
            load_B(2, stg0 + 2 * STAGE_BYTES); asm volatile("cp.async.commit_group;");
        }

        // ---- epilogue: register-resident cell update, gate-interleaved cols ----
        const float w0 = s_wout[hloc], w1 = s_wout[hloc + 1];
        const int hb = j0 + hloc;
#pragma unroll
        for (int mt = 0; mt < 2; ++mt)
#pragma unroll
            for (int eh = 0; eh < 2; ++eh) {
                const int rl = wM * 32 + mt * 16 + (lane >> 2) + eh * 8;
                const float xv = s_x[rl];
                float hn[2];
#pragma unroll
                for (int ej = 0; ej < 2; ++ej) {
                    const int e = eh * 2 + ej;
                    float gi = acc[mt][0][e] + xv * wih_r[0][ej] + bsum_r[0][ej];
                    float gf = acc[mt][1][e] + xv * wih_r[1][ej] + bsum_r[1][ej];
                    float gg = acc[mt][2][e] + xv * wih_r[2][ej] + bsum_r[2][ej];
                    float go = acc[mt][3][e] + xv * wih_r[3][ej] + bsum_r[3][ej];
                    float co = c_reg[mt][eh][ej];
                    float cn = sigf(gf) * co + sigf(gi) * tanhf_fast(gg);
                    hn[ej] = sigf(go) * tanhf_fast(cn);
                    c_reg[mt][eh][ej] = cn;
                }
                // packed bf16x2 store of h
                __nv_bfloat162 hv = __floats2bfloat162_rn(hn[0], hn[1]);
                *(uint32_t*)&g_hh[wbuf][(size_t)(m0 + rl) * HID + hb] =
                    *(uint32_t*)&hv;
                // readout partial over this thread's 2 hidden units
                float p = hn[0] * w0 + hn[1] * w1;
                p += __shfl_xor_sync(0xFFFFFFFFu, p, 1);
                p += __shfl_xor_sync(0xFFFFFFFFu, p, 2);
                if ((lane & 3) == 0) s_pred[wN * 128 + rl] = p;
            }
        __syncthreads();
        if (tid < 128) {
            float p = s_pred[tid] + s_pred[128 + tid] + s_pred[256 + tid] + s_pred[384 + tid];
            g_parts[wbuf][jb * BATCH + m0 + tid] = p;
        }

        // ---- grid barrier ----
        bar_target += NCTA;
        __threadfence();
        __syncthreads();
        if (tid == 0) {
            atomicAdd(&g_bar, 1u);
            while (*((volatile unsigned*)&g_bar) < bar_target) { __nanosleep(32); }
        }
        __syncthreads();
    }

    // ---- final prediction ----
    if (jb == 0 && tid < 128) {
        const int lbuf = (total - 1) & 1;
        float acc2 = 0.0f;
#pragma unroll 8
        for (int p = 0; p < 32; ++p)
            acc2 += __ldcg(&g_parts[lbuf][p * BATCH + m0 + tid]);
        out[(size_t)(m0 + tid) * steps + (steps - 1)] = acc2 + bout;
    }
}

// ---------------- launch ----------------
extern "C" void kernel_launch(void* const* d_in, const int* in_sizes, int n_in,
                              void* d_out, int out_size) {
    const float* data  = (const float*)d_in[0];  // [B, T, 1]
    const float* W_ih  = (const float*)d_in[1];  // [4H, 1]
    const float* W_hh  = (const float*)d_in[2];  // [4H, H]
    const float* b_ih  = (const float*)d_in[3];
    const float* b_hh  = (const float*)d_in[4];
    const float* W_out = (const float*)d_in[5];  // [1, H]
    const float* b_out = (const float*)d_in[6];
    float* out = (float*)d_out;                  // [B, STEPS, 1]

    int T     = in_sizes[0] / BATCH;   // 64
    int steps = out_size / BATCH;      // 96

    cudaFuncSetAttribute(lstm_persist, cudaFuncAttributeMaxDynamicSharedMemorySize, SMEM_TOTAL);

    prep_split_kernel<<<2048, 512>>>(W_hh);
    init_zero_kernel<<<512, 512>>>();

    lstm_persist<<<NCTA, NTHREADS, SMEM_TOTAL>>>(data, W_ih, b_ih, b_hh,
                                                 W_out, b_out, out, T, steps);
}

// round 11
// speedup vs baseline: 4.3781x; 1.5667x over previous
#include <cuda_runtime.h>
#include <cuda_bf16.h>
#include <cstdint>
#include <math.h>

#define BATCH 512
#define HID   1024
#define GATES 4096
#define TILEM 128          // batch rows per CTA
#define NH    32           // hidden units per CTA (-> 128 gate cols, gate-interleaved)
#define KC    64           // K chunk (bf16 elems), 128B rows
#define NCHUNK (HID / KC)  // 16
#define NTHREADS 512       // 16 warps, warp tile 32x32
#define NCTA  128          // (BATCH/TILEM) * (HID/NH)

// ---- shared memory layout (bytes) ----
#define SO_X      0         // 128 f32
#define SO_WOUT   512       // 32 f32
#define SO_PRED   640       // 4*128 f32
#define SO_STAGE  4096      // 1024-aligned
#define STAGE_BYTES 32768   // A(16KB) + B(16KB)
#define TO_AHI    0
#define TO_BHI    16384
#define SMEM_TOTAL (SO_STAGE + 4 * STAGE_BYTES)   // 135168

// column mapping within a CTA's 128 gate-cols: n -> gate=(n>>3)&3, hid=(n&7)+((n>>5)<<3)
// ---------------- device scratch ----------------
__device__ __align__(128) __nv_bfloat16  g_hh  [2][BATCH * HID];   // double-buffered h (bf16)
__device__ __align__(128) __nv_bfloat16  g_Whi [GATES * HID];
__device__ __align__(128) float          g_parts[2][32 * BATCH];   // double-buffered readout partials
__device__ unsigned g_bar;

// ---------------- helpers ----------------
__device__ __forceinline__ uint32_t smem_u32(const void* p) {
    uint32_t a;
    asm("{ .reg .u64 t; cvta.to.shared.u64 t, %1; cvt.u32.u64 %0, t; }" : "=r"(a) : "l"(p));
    return a;
}
__device__ __forceinline__ void cp16(uint32_t dst, const void* src) {
    asm volatile("cp.async.cg.shared.global [%0], [%1], 16;"
                 :: "r"(dst), "l"(__cvta_generic_to_global(src)));
}
__device__ __forceinline__ uint32_t swz(uint32_t off) { return off ^ ((off >> 3) & 0x70); }

__device__ __forceinline__ void ldsm4(uint32_t* r, uint32_t a) {
    asm volatile("ldmatrix.sync.aligned.m8n8.x4.shared.b16 {%0,%1,%2,%3}, [%4];"
                 : "=r"(r[0]), "=r"(r[1]), "=r"(r[2]), "=r"(r[3]) : "r"(a));
}
__device__ __forceinline__ void hmma(float* c, const uint32_t* a, const uint32_t* b) {
    asm volatile("mma.sync.aligned.m16n8k16.row.col.f32.bf16.bf16.f32 "
                 "{%0,%1,%2,%3}, {%4,%5,%6,%7}, {%8,%9}, {%0,%1,%2,%3};"
                 : "+f"(c[0]), "+f"(c[1]), "+f"(c[2]), "+f"(c[3])
                 : "r"(a[0]), "r"(a[1]), "r"(a[2]), "r"(a[3]), "r"(b[0]), "r"(b[1]));
}
__device__ __forceinline__ float sigf(float x) {
    return __fdividef(1.0f, 1.0f + __expf(-x));
}
__device__ __forceinline__ float tanhf_fast(float x) {
    float ax = fabsf(x);
    float e  = __expf(-2.0f * ax);
    float t  = __fdividef(1.0f - e, 1.0f + e);
    return copysignf(t, x);
}

// ---------------- prep / init ----------------
__global__ void prep_split_kernel(const float* __restrict__ W) {
    int n = GATES * HID;
    for (int i = blockIdx.x * blockDim.x + threadIdx.x; i < n; i += gridDim.x * blockDim.x) {
        g_Whi[i] = __float2bfloat16(W[i]);
    }
}
__global__ void init_zero_kernel() {
    int n = BATCH * HID;
    __nv_bfloat16 z = __float2bfloat16(0.0f);
    for (int i = blockIdx.x * blockDim.x + threadIdx.x; i < n; i += gridDim.x * blockDim.x) {
        g_hh[0][i] = z; g_hh[1][i] = z;
    }
    if (blockIdx.x == 0 && threadIdx.x == 0) g_bar = 0u;
}

// ---------------- persistent LSTM kernel ----------------
__global__ void __launch_bounds__(NTHREADS, 1)
lstm_persist(const float* __restrict__ data, const float* __restrict__ W_ih,
             const float* __restrict__ b_ih, const float* __restrict__ b_hh,
             const float* __restrict__ W_out, const float* __restrict__ b_out,
             float* __restrict__ out, int T, int steps)
{
    extern __shared__ __align__(1024) char sm[];
    const uint32_t sb = smem_u32(sm);
    const int tid  = threadIdx.x;
    const int wid  = tid >> 5;
    const int lane = tid & 31;
    const int mb = blockIdx.x & 3;
    const int jb = blockIdx.x >> 2;
    const int m0 = mb * TILEM;
    const int j0 = jb * NH;
    const int wM = wid & 3;        // 0..3 -> 32-row slab
    const int wN = wid >> 2;       // 0..3 -> 32-col slab (8 hidden units x 4 gates)

    float* s_x    = (float*)(sm + SO_X);
    float* s_wout = (float*)(sm + SO_WOUT);
    float* s_pred = (float*)(sm + SO_PRED);

    // ---- one-time: per-thread gate weights/biases + wout, c state in regs ----
    const int hloc = wN * 8 + 2 * (lane & 3);   // local hidden base (2 units)
    float wih_r[4][2], bsum_r[4][2];
#pragma unroll
    for (int gt = 0; gt < 4; ++gt)
#pragma unroll
        for (int ej = 0; ej < 2; ++ej) {
            int j = gt * HID + j0 + hloc + ej;
            wih_r[gt][ej]  = W_ih[j];
            bsum_r[gt][ej] = b_ih[j] + b_hh[j];
        }
    if (tid < 32) s_wout[tid] = W_out[j0 + tid];
    const float bout = b_out[0];
    float c_reg[2][2][2];   // [mt][eh][ej]
#pragma unroll
    for (int a = 0; a < 2; ++a)
#pragma unroll
        for (int b = 0; b < 2; ++b)
#pragma unroll
            for (int d = 0; d < 2; ++d) c_reg[a][b][d] = 0.0f;

    // per-thread ldmatrix UNSWIZZLED base offsets
    const uint32_t aU = (uint32_t)((wM * 32 + (lane & 15)) * 128 + ((lane >> 4) * 8) * 2);
    const uint32_t bU = (uint32_t)((wN * 32 + (lane & 7) + ((lane >> 4) << 3)) * 128
                                   + (((lane >> 3) & 1) * 8) * 2);
    const uint32_t stg0 = sb + SO_STAGE;

    // ---- loaders ----
    // gate-interleaved B row r -> W row: gate=(r>>3)&3, hid=(r&7)+((r>>5)<<3)
    auto load_B = [&](int chunk, uint32_t stg) {
        const int k0 = chunk * KC;
#pragma unroll
        for (int it = 0; it < 2; ++it) {
            int li = it * NTHREADS + tid;
            int r = li >> 3, c16 = li & 7;
            uint32_t soff = swz((uint32_t)(r * 128 + c16 * 16));
            int wrow = ((r >> 3) & 3) * HID + j0 + (r & 7) + ((r >> 5) << 3);
            size_t boff = (size_t)wrow * HID + k0 + c16 * 8;
            cp16(stg + TO_BHI + soff, g_Whi + boff);
        }
    };
    auto load_A = [&](const __nv_bfloat16* hsrc, int chunk, uint32_t stg) {
        const int k0 = chunk * KC;
#pragma unroll
        for (int it = 0; it < 2; ++it) {
            int li = it * NTHREADS + tid;
            int r = li >> 3, c16 = li & 7;
            uint32_t soff = swz((uint32_t)(r * 128 + c16 * 16));
            size_t aoff = (size_t)(m0 + r) * HID + k0 + c16 * 8;
            cp16(stg + TO_AHI + soff, hsrc + aoff);
        }
    };

    const int total = T + steps - 1;   // 159 cell steps
    unsigned bar_target = 0;
    __syncthreads();

    // prefetch B chunks 0..2 for the first step
    load_B(0, stg0 + 0 * STAGE_BYTES); asm volatile("cp.async.commit_group;");
    load_B(1, stg0 + 1 * STAGE_BYTES); asm volatile("cp.async.commit_group;");
    load_B(2, stg0 + 2 * STAGE_BYTES); asm volatile("cp.async.commit_group;");

    for (int g = 0; g < total; ++g) {
        const int rbuf = (g & 1) ^ 1;
        const int wbuf = g & 1;
        const __nv_bfloat16* hsrc = g_hh[rbuf];

        // ---- per-step prologue: x into SMEM (+ out write for AR steps) ----
        if (tid < 128) {
            float xv;
            if (g < T) {
                xv = data[(size_t)(m0 + tid) * T + g];
            } else {
                float acc2 = 0.0f;
#pragma unroll 8
                for (int p = 0; p < 32; ++p)
                    acc2 += __ldcg(&g_parts[rbuf][p * BATCH + m0 + tid]);
                xv = acc2 + bout;
                if (jb == 0) out[(size_t)(m0 + tid) * steps + (g - T)] = xv;
            }
            s_x[tid] = xv;
        }

        // ---- prime A chunks 0..2 (B already prefetched pre-barrier) ----
        load_A(hsrc, 0, stg0 + 0 * STAGE_BYTES); asm volatile("cp.async.commit_group;");
        load_A(hsrc, 1, stg0 + 1 * STAGE_BYTES); asm volatile("cp.async.commit_group;");
        load_A(hsrc, 2, stg0 + 2 * STAGE_BYTES); asm volatile("cp.async.commit_group;");

        float acc[2][4][4];
#pragma unroll
        for (int mt = 0; mt < 2; ++mt)
#pragma unroll
            for (int nt = 0; nt < 4; ++nt)
#pragma unroll
                for (int e = 0; e < 4; ++e) acc[mt][nt][e] = 0.0f;

#pragma unroll 1
        for (int i = 0; i < NCHUNK; ++i) {
            if (i < NCHUNK - 2)       asm volatile("cp.async.wait_group 2;");
            else if (i == NCHUNK - 2) asm volatile("cp.async.wait_group 1;");
            else                      asm volatile("cp.async.wait_group 0;");
            __syncthreads();
            {
                const uint32_t stg = stg0 + (i & 3) * STAGE_BYTES;
#pragma unroll
                for (int k16 = 0; k16 < 4; ++k16) {
                    const uint32_t ko = (uint32_t)k16 * 32;
                    uint32_t aHi[2][4];
#pragma unroll
                    for (int mt = 0; mt < 2; ++mt) {
                        uint32_t so = swz(aU + (uint32_t)mt * 2048 + ko);
                        ldsm4(aHi[mt], stg + TO_AHI + so);
                    }
                    uint32_t bH[4][2];
#pragma unroll
                    for (int half = 0; half < 2; ++half) {
                        uint32_t so = swz(bU + (uint32_t)half * 2048 + ko);
                        uint32_t t[4];
                        ldsm4(t, stg + TO_BHI + so);
                        bH[half*2][0] = t[0]; bH[half*2][1] = t[1];
                        bH[half*2+1][0] = t[2]; bH[half*2+1][1] = t[3];
                    }
#pragma unroll
                    for (int mt = 0; mt < 2; ++mt)
#pragma unroll
                        for (int nt = 0; nt < 4; ++nt)
                            hmma(acc[mt][nt], aHi[mt], bH[nt]);
                }
            }
            if (i + 3 < NCHUNK) {
                uint32_t stg = stg0 + ((i + 3) & 3) * STAGE_BYTES;
                load_A(hsrc, i + 3, stg);
                load_B(i + 3, stg);
                asm volatile("cp.async.commit_group;");
            }
        }

        // ---- prefetch next step's B chunks 0..2 (overlaps epilogue + barrier) ----
        if (g + 1 < total) {
            load_B(0, stg0 + 0 * STAGE_BYTES); asm volatile("cp.async.commit_group;");
            load_B(1, stg0 + 1 * STAGE_BYTES); asm volatile("cp.async.commit_group;");
            load_B(2, stg0 + 2 * STAGE_BYTES); asm volatile("cp.async.commit_group;");
        }

        // ---- epilogue: register-resident cell update, gate-interleaved cols ----
        const float w0 = s_wout[hloc], w1 = s_wout[hloc + 1];
        const int hb = j0 + hloc;
#pragma unroll
        for (int mt = 0; mt < 2; ++mt)
#pragma unroll
            for (int eh = 0; eh < 2; ++eh) {
                const int rl = wM * 32 + mt * 16 + (lane >> 2) + eh * 8;
                const float xv = s_x[rl];
                float hn[2];
#pragma unroll
                for (int ej = 0; ej < 2; ++ej) {
                    const int e = eh * 2 + ej;
                    float gi = acc[mt][0][e] + xv * wih_r[0][ej] + bsum_r[0][ej];
                    float gf = acc[mt][1][e] + xv * wih_r[1][ej] + bsum_r[1][ej];
                    float gg = acc[mt][2][e] + xv * wih_r[2][ej] + bsum_r[2][ej];
                    float go = acc[mt][3][e] + xv * wih_r[3][ej] + bsum_r[3][ej];
                    float co = c_reg[mt][eh][ej];
                    float cn = sigf(gf) * co + sigf(gi) * tanhf_fast(gg);
                    hn[ej] = sigf(go) * tanhf_fast(cn);
                    c_reg[mt][eh][ej] = cn;
                }
                __nv_bfloat162 hv = __floats2bfloat162_rn(hn[0], hn[1]);
                *(uint32_t*)&g_hh[wbuf][(size_t)(m0 + rl) * HID + hb] =
                    *(uint32_t*)&hv;
                float p = hn[0] * w0 + hn[1] * w1;
                p += __shfl_xor_sync(0xFFFFFFFFu, p, 1);
                p += __shfl_xor_sync(0xFFFFFFFFu, p, 2);
                if ((lane & 3) == 0) s_pred[wN * 128 + rl] = p;
            }
        __syncthreads();
        if (tid < 128) {
            float p = s_pred[tid] + s_pred[128 + tid] + s_pred[256 + tid] + s_pred[384 + tid];
            g_parts[wbuf][jb * BATCH + m0 + tid] = p;
        }

        // ---- grid barrier ----
        bar_target += NCTA;
        __threadfence();
        __syncthreads();
        if (tid == 0) {
            atomicAdd(&g_bar, 1u);
            while (*((volatile unsigned*)&g_bar) < bar_target) { __nanosleep(32); }
        }
        __syncthreads();
    }

    // ---- final prediction ----
    if (jb == 0 && tid < 128) {
        const int lbuf = (total - 1) & 1;
        float acc2 = 0.0f;
#pragma unroll 8
        for (int p = 0; p < 32; ++p)
            acc2 += __ldcg(&g_parts[lbuf][p * BATCH + m0 + tid]);
        out[(size_t)(m0 + tid) * steps + (steps - 1)] = acc2 + bout;
    }
}

// ---------------- launch ----------------
extern "C" void kernel_launch(void* const* d_in, const int* in_sizes, int n_in,
                              void* d_out, int out_size) {
    const float* data  = (const float*)d_in[0];  // [B, T, 1]
    const float* W_ih  = (const float*)d_in[1];  // [4H, 1]
    const float* W_hh  = (const float*)d_in[2];  // [4H, H]
    const float* b_ih  = (const float*)d_in[3];
    const float* b_hh  = (const float*)d_in[4];
    const float* W_out = (const float*)d_in[5];  // [1, H]
    const float* b_out = (const float*)d_in[6];
    float* out = (float*)d_out;                  // [B, STEPS, 1]

    int T     = in_sizes[0] / BATCH;   // 64
    int steps = out_size / BATCH;      // 96

    cudaFuncSetAttribute(lstm_persist, cudaFuncAttributeMaxDynamicSharedMemorySize, SMEM_TOTAL);

    prep_split_kernel<<<2048, 512>>>(W_hh);
    init_zero_kernel<<<512, 512>>>();

    lstm_persist<<<NCTA, NTHREADS, SMEM_TOTAL>>>(data, W_ih, b_ih, b_hh,
                                                 W_out, b_out, out, T, steps);
}